// round 10
// baseline (speedup 1.0000x reference)
#include <cuda_runtime.h>
#include <cuda_bf16.h>
#include <cuda_fp16.h>
#include <cstdint>

#define N_NODES 50000
#define N_EDGES 1600000
#define CDIM 128
#define N_LAYERS 8

// ---------------- scratch (device globals; no allocation allowed) ----------
__device__ float  g_h [N_NODES * CDIM];        // fp32 node features (residual / fc0 input)
__device__ __half g_hhb[2][N_NODES * CDIM];    // double-buffered fp16 gather tables
__device__ float  g_A [N_NODES * CDIM];
__device__ float  g_B [N_NODES * CDIM];
__device__ float  g_dis[N_NODES];
__device__ int    g_deg[N_NODES];
__device__ int    g_indptr[N_NODES + 1];
__device__ int    g_cursor[N_NODES];
__device__ int    g_csr_src[N_EDGES];
__device__ float  g_csr_nrm[N_EDGES];
// transposed + hi/lo-split weights for node GEMMs: [10][n=128][k=128]
__device__ __nv_bfloat16 g_Wth[10 * 128 * 128];
__device__ __nv_bfloat16 g_Wtl[10 * 128 * 128];

// ---------------- helpers ----------------------------------------------------
__device__ __forceinline__ void mma_bf16(float d[4], const uint32_t a[4],
                                         uint32_t b0, uint32_t b1) {
    asm volatile(
        "mma.sync.aligned.m16n8k16.row.col.f32.bf16.bf16.f32 "
        "{%0,%1,%2,%3}, {%4,%5,%6,%7}, {%8,%9}, {%0,%1,%2,%3};"
        : "+f"(d[0]), "+f"(d[1]), "+f"(d[2]), "+f"(d[3])
        : "r"(a[0]), "r"(a[1]), "r"(a[2]), "r"(a[3]), "r"(b0), "r"(b1));
}
__device__ __forceinline__ void mma_fp16(float d[4], const uint32_t a[4],
                                         uint32_t b0, uint32_t b1) {
    asm volatile(
        "mma.sync.aligned.m16n8k16.row.col.f32.f16.f16.f32 "
        "{%0,%1,%2,%3}, {%4,%5,%6,%7}, {%8,%9}, {%0,%1,%2,%3};"
        : "+f"(d[0]), "+f"(d[1]), "+f"(d[2]), "+f"(d[3])
        : "r"(a[0]), "r"(a[1]), "r"(a[2]), "r"(a[3]), "r"(b0), "r"(b1));
}
__device__ __forceinline__ void ldmx4(uint32_t r[4], uint32_t addr) {
    asm volatile("ldmatrix.sync.aligned.m8n8.x4.shared.b16 {%0,%1,%2,%3}, [%4];"
                 : "=r"(r[0]), "=r"(r[1]), "=r"(r[2]), "=r"(r[3]) : "r"(addr));
}
__device__ __forceinline__ uint32_t pack_bf16(float a, float b) {
    uint32_t lo = (uint32_t)__bfloat16_as_ushort(__float2bfloat16(a));
    uint32_t hi = (uint32_t)__bfloat16_as_ushort(__float2bfloat16(b));
    return lo | (hi << 16);
}
// accumulate 4 fp16 channels (uint2) scaled by nr into float4
__device__ __forceinline__ void acc_h4(float4& acc, uint2 raw, float nr) {
    __half2 h0 = *(__half2*)&raw.x;
    __half2 h1 = *(__half2*)&raw.y;
    float2 f0 = __half22float2(h0);
    float2 f1 = __half22float2(h1);
    acc.x += nr * f0.x; acc.y += nr * f0.y;
    acc.z += nr * f1.x; acc.w += nr * f1.y;
}

// ---------------- setup kernels ---------------------------------------------
__global__ void k_zero_deg() {
    int i = blockIdx.x * blockDim.x + threadIdx.x;
    if (i < N_NODES) g_deg[i] = 0;
}

__global__ void k_count_deg(const int* __restrict__ col) {
    int e = blockIdx.x * blockDim.x + threadIdx.x;
    if (e < N_EDGES) atomicAdd(&g_deg[col[e]], 1);
}

__global__ void k_cvt_x(const float* __restrict__ x) {
    int i = blockIdx.x * blockDim.x + threadIdx.x;
    if (i < N_NODES * CDIM / 2) {
        float2 v = ((const float2*)x)[i];
        ((__half2*)g_hhb[0])[i] = __floats2half2_rn(v.x, v.y);
    }
}

__global__ void k_scan_dis() {
    __shared__ int sbuf[1024];
    __shared__ int s_carry;
    int t = threadIdx.x;
    if (t == 0) s_carry = 0;
    __syncthreads();
    for (int base = 0; base < N_NODES; base += 1024) {
        int idx = base + t;
        int v = (idx < N_NODES) ? g_deg[idx] : 0;
        sbuf[t] = v;
        __syncthreads();
        for (int off = 1; off < 1024; off <<= 1) {
            int y = (t >= off) ? sbuf[t - off] : 0;
            __syncthreads();
            sbuf[t] += y;
            __syncthreads();
        }
        int incl = sbuf[t];
        int carry = s_carry;
        if (idx < N_NODES) {
            int excl = carry + incl - v;
            g_indptr[idx] = excl;
            g_cursor[idx] = excl;
            g_dis[idx] = rsqrtf((float)(v + 1));
        }
        __syncthreads();
        if (t == 1023) s_carry = carry + sbuf[1023];
        __syncthreads();
    }
    if (t == 0) g_indptr[N_NODES] = s_carry;
}

__global__ void k_fill_csr(const int* __restrict__ row, const int* __restrict__ col) {
    int e = blockIdx.x * blockDim.x + threadIdx.x;
    if (e < N_EDGES) {
        int r = row[e], c = col[e];
        float nrm = g_dis[r] * g_dis[c];
        int pos = atomicAdd(&g_cursor[c], 1);
        g_csr_src[pos] = r;
        g_csr_nrm[pos] = nrm;
    }
}

// ---------------- W transpose + bf16 hi/lo split (once) ---------------------
__global__ void k_split_w(const float* __restrict__ convs_W,
                          const float* __restrict__ fc0_W) {
    int idx = blockIdx.x * 256 + threadIdx.x;
    if (idx >= 10 * 16384) return;
    int l = idx >> 14;
    int kk = (idx >> 7) & 127;
    int n = idx & 127;
    float v = (l < 8) ? convs_W[idx] : fc0_W[idx - 8 * 16384];
    __nv_bfloat16 hi = __float2bfloat16(v);
    float lo = v - __bfloat162float(hi);
    int dst = (l << 14) + (n << 7) + kk;
    g_Wth[dst] = hi;
    g_Wtl[dst] = __float2bfloat16(lo);
}

// ---------------- shared GEMM smem layout ------------------------------------
#define SGT_XH 0
#define SGT_XL 17408
#define SGT_WH 34816
#define SGT_WL 69632
#define SGT_BYTES 104448

// ---------------- fused GCN layer: h = relu((A_hat h) W + b [+h]) -----------
// CTA: 64 nodes, 256 thr/8 warps. Phase A: warp-per-node gather-aggregate
// m = A_hat h from fp16 table buffer rb (read-only this layer). Phase B:
// 3-pass bf16 MMA. Epilogue -> g_h fp32 AND fp16 table buffer rb^1.
__global__ void __launch_bounds__(256, 2) k_gcn_layer(
    int layer, const float* __restrict__ bias, int residual, int rb) {
    extern __shared__ char smc[];
    int tid = threadIdx.x;
    int lane = tid & 31, wid = tid >> 5;
    int rowBase = blockIdx.x * 64;

    // --- stage W hi/lo (pre-transposed [n][k]) -------------------------------
    {
        const uint4* Wh4 = (const uint4*)(g_Wth + layer * 16384);
        const uint4* Wl4 = (const uint4*)(g_Wtl + layer * 16384);
#pragma unroll
        for (int i = 0; i < 8; i++) {
            int idx = tid + i * 256;
            int rr = idx >> 4, c8 = idx & 15;
            *(uint4*)(smc + SGT_WH + rr * 272 + c8 * 16) = Wh4[rr * 16 + c8];
            *(uint4*)(smc + SGT_WL + rr * 272 + c8 * 16) = Wl4[rr * 16 + c8];
        }
    }

    // --- Phase A: gather-aggregate m = A_hat h, write X hi/lo ----------------
    {
        const uint2* hw2 = (const uint2*)g_hhb[rb];
        uint32_t* Xh32 = (uint32_t*)(smc + SGT_XH);
        uint32_t* Xl32 = (uint32_t*)(smc + SGT_XL);
#pragma unroll 2
        for (int j = 0; j < 8; j++) {
            int rr = wid * 8 + j;
            int n = rowBase + rr;
            float4 acc = make_float4(0.f, 0.f, 0.f, 0.f);
            if (n < N_NODES) {
                float d = g_dis[n];
                acc_h4(acc, hw2[n * 32 + lane], d * d);   // self term
                int e = g_indptr[n];
                int end = g_indptr[n + 1];
                for (; e + 8 <= end; e += 8) {
                    int s[8]; float nr[8]; uint2 v[8];
#pragma unroll
                    for (int q = 0; q < 8; q++) { s[q] = g_csr_src[e + q]; nr[q] = g_csr_nrm[e + q]; }
#pragma unroll
                    for (int q = 0; q < 8; q++) v[q] = hw2[s[q] * 32 + lane];
#pragma unroll
                    for (int q = 0; q < 8; q++) acc_h4(acc, v[q], nr[q]);
                }
                if (e + 4 <= end) {
                    int s[4]; float nr[4]; uint2 v[4];
#pragma unroll
                    for (int q = 0; q < 4; q++) { s[q] = g_csr_src[e + q]; nr[q] = g_csr_nrm[e + q]; }
#pragma unroll
                    for (int q = 0; q < 4; q++) v[q] = hw2[s[q] * 32 + lane];
#pragma unroll
                    for (int q = 0; q < 4; q++) acc_h4(acc, v[q], nr[q]);
                    e += 4;
                }
                for (; e < end; e++)
                    acc_h4(acc, hw2[g_csr_src[e] * 32 + lane], g_csr_nrm[e]);
            }
            // bf16 hi/lo split -> smem X tile (channels lane*4 .. lane*4+3)
            __nv_bfloat16 h0 = __float2bfloat16(acc.x);
            __nv_bfloat16 h1 = __float2bfloat16(acc.y);
            __nv_bfloat16 h2 = __float2bfloat16(acc.z);
            __nv_bfloat16 h3 = __float2bfloat16(acc.w);
            uint32_t hp0 = (uint32_t)__bfloat16_as_ushort(h0) |
                           ((uint32_t)__bfloat16_as_ushort(h1) << 16);
            uint32_t hp1 = (uint32_t)__bfloat16_as_ushort(h2) |
                           ((uint32_t)__bfloat16_as_ushort(h3) << 16);
            uint32_t lp0 = pack_bf16(acc.x - __bfloat162float(h0), acc.y - __bfloat162float(h1));
            uint32_t lp1 = pack_bf16(acc.z - __bfloat162float(h2), acc.w - __bfloat162float(h3));
            int o = rr * 68 + lane * 2;
            *(uint2*)&Xh32[o] = make_uint2(hp0, hp1);
            *(uint2*)&Xl32[o] = make_uint2(lp0, lp1);
        }
    }
    __syncthreads();

    // --- Phase B: 3-pass bf16 MMA --------------------------------------------
    int g = lane >> 2, tg = lane & 3;
    int rblk = wid >> 1, cblk = wid & 1;

    float acc[8][4];
#pragma unroll
    for (int n = 0; n < 8; n++)
#pragma unroll
        for (int j = 0; j < 4; j++) acc[n][j] = 0.f;

    uint32_t xh_sb = (uint32_t)__cvta_generic_to_shared(smc + SGT_XH);
    uint32_t xl_sb = (uint32_t)__cvta_generic_to_shared(smc + SGT_XL);
    uint32_t wh_sb = (uint32_t)__cvta_generic_to_shared(smc + SGT_WH);
    uint32_t wl_sb = (uint32_t)__cvta_generic_to_shared(smc + SGT_WL);

    int a_r = rblk * 16 + (lane & 7) + (lane & 8);
    int a_kel = (lane & 16) ? 8 : 0;
    uint32_t a_hi_base = xh_sb + (uint32_t)(a_r * 272 + a_kel * 2);
    uint32_t a_lo_base = xl_sb + (uint32_t)(a_r * 272 + a_kel * 2);
    int b_nloc = (lane & 7) + ((lane & 16) >> 1);
    int b_kel = (lane & 8);
    uint32_t b_rowoff = (uint32_t)((cblk * 64 + b_nloc) * 272 + b_kel * 2);

#pragma unroll
    for (int k = 0; k < 8; k++) {
        uint32_t ah[4], al[4];
        ldmx4(ah, a_hi_base + k * 32);
        ldmx4(al, a_lo_base + k * 32);
        uint32_t bh[4][4], bl[4][4];
#pragma unroll
        for (int nb2 = 0; nb2 < 4; nb2++) {
            uint32_t off = b_rowoff + (uint32_t)(nb2 * 16 * 272) + k * 32;
            ldmx4(bh[nb2], wh_sb + off);
            ldmx4(bl[nb2], wl_sb + off);
        }
#pragma unroll
        for (int nb = 0; nb < 8; nb++) {
            uint32_t b0h = bh[nb >> 1][(nb & 1) * 2], b1h = bh[nb >> 1][(nb & 1) * 2 + 1];
            uint32_t b0l = bl[nb >> 1][(nb & 1) * 2], b1l = bl[nb >> 1][(nb & 1) * 2 + 1];
            mma_bf16(acc[nb], ah, b0h, b1h);
            mma_bf16(acc[nb], al, b0h, b1h);
            mma_bf16(acc[nb], ah, b0l, b1l);
        }
    }

    // --- epilogue: relu(+bias[+res]) -> g_h fp32 AND fp16 table rb^1 ---------
    int r0 = rowBase + rblk * 16 + g;
    __half2* oh = (__half2*)g_hhb[rb ^ 1];
#pragma unroll
    for (int nb = 0; nb < 8; nb++) {
        int c = cblk * 64 + nb * 8 + 2 * tg;
        float bv0 = bias[c], bv1 = bias[c + 1];
        if (r0 < N_NODES) {
            float v0 = acc[nb][0] + bv0, v1 = acc[nb][1] + bv1;
            if (residual) { v0 += g_h[r0 * 128 + c]; v1 += g_h[r0 * 128 + c + 1]; }
            v0 = fmaxf(v0, 0.f); v1 = fmaxf(v1, 0.f);
            *(float2*)&g_h[r0 * 128 + c] = make_float2(v0, v1);
            oh[(r0 * 128 + c) >> 1] = __floats2half2_rn(v0, v1);
        }
        if (r0 + 8 < N_NODES) {
            float v2 = acc[nb][2] + bv0, v3 = acc[nb][3] + bv1;
            if (residual) { v2 += g_h[(r0 + 8) * 128 + c]; v3 += g_h[(r0 + 8) * 128 + c + 1]; }
            v2 = fmaxf(v2, 0.f); v3 = fmaxf(v3, 0.f);
            *(float2*)&g_h[(r0 + 8) * 128 + c] = make_float2(v2, v3);
            oh[((r0 + 8) * 128 + c) >> 1] = __floats2half2_rn(v2, v3);
        }
    }
}

// ---------------- tensor-core node GEMM for fc0 (bf16x2 3-pass) -------------
// out[M,128] = g_h[M,128] @ W_l[128,128] (+bias). out_sel: 1 -> g_A, 2 -> g_B.
__global__ void __launch_bounds__(256, 2) k_sgemm_tc(
    int out_sel, int layer, const float* __restrict__ bias, int M) {
    extern __shared__ char smc[];
    float* out = (out_sel == 1) ? g_A : g_B;

    int tid = threadIdx.x;
    int lane = tid & 31, wid = tid >> 5;
    int rowBase = blockIdx.x * 64;

    // --- stage X split (64 x 128 fp32 -> hi/lo bf16, stride 136) ------------
    {
        const float4* A4 = (const float4*)g_h;
        uint32_t* Xh32 = (uint32_t*)(smc + SGT_XH);
        uint32_t* Xl32 = (uint32_t*)(smc + SGT_XL);
#pragma unroll
        for (int i = 0; i < 8; i++) {
            int idx = tid + i * 256;
            int rr = idx >> 5, c4 = idx & 31;
            float4 v = make_float4(0.f, 0.f, 0.f, 0.f);
            if (rowBase + rr < M) v = A4[(rowBase + rr) * 32 + c4];
            __nv_bfloat16 h0 = __float2bfloat16(v.x);
            __nv_bfloat16 h1 = __float2bfloat16(v.y);
            __nv_bfloat16 h2 = __float2bfloat16(v.z);
            __nv_bfloat16 h3 = __float2bfloat16(v.w);
            uint32_t hp0 = (uint32_t)__bfloat16_as_ushort(h0) |
                           ((uint32_t)__bfloat16_as_ushort(h1) << 16);
            uint32_t hp1 = (uint32_t)__bfloat16_as_ushort(h2) |
                           ((uint32_t)__bfloat16_as_ushort(h3) << 16);
            uint32_t lp0 = pack_bf16(v.x - __bfloat162float(h0), v.y - __bfloat162float(h1));
            uint32_t lp1 = pack_bf16(v.z - __bfloat162float(h2), v.w - __bfloat162float(h3));
            int o = rr * 68 + c4 * 2;
            *(uint2*)&Xh32[o] = make_uint2(hp0, hp1);
            *(uint2*)&Xl32[o] = make_uint2(lp0, lp1);
        }
    }
    // --- stage W hi/lo -------------------------------------------------------
    {
        const uint4* Wh4 = (const uint4*)(g_Wth + layer * 16384);
        const uint4* Wl4 = (const uint4*)(g_Wtl + layer * 16384);
#pragma unroll
        for (int i = 0; i < 8; i++) {
            int idx = tid + i * 256;
            int rr = idx >> 4, c8 = idx & 15;
            *(uint4*)(smc + SGT_WH + rr * 272 + c8 * 16) = Wh4[rr * 16 + c8];
            *(uint4*)(smc + SGT_WL + rr * 272 + c8 * 16) = Wl4[rr * 16 + c8];
        }
    }
    __syncthreads();

    int g = lane >> 2, tg = lane & 3;
    int rblk = wid >> 1, cblk = wid & 1;

    float acc[8][4];
#pragma unroll
    for (int n = 0; n < 8; n++)
#pragma unroll
        for (int j = 0; j < 4; j++) acc[n][j] = 0.f;

    uint32_t xh_sb = (uint32_t)__cvta_generic_to_shared(smc + SGT_XH);
    uint32_t xl_sb = (uint32_t)__cvta_generic_to_shared(smc + SGT_XL);
    uint32_t wh_sb = (uint32_t)__cvta_generic_to_shared(smc + SGT_WH);
    uint32_t wl_sb = (uint32_t)__cvta_generic_to_shared(smc + SGT_WL);

    int a_r = rblk * 16 + (lane & 7) + (lane & 8);
    int a_kel = (lane & 16) ? 8 : 0;
    uint32_t a_hi_base = xh_sb + (uint32_t)(a_r * 272 + a_kel * 2);
    uint32_t a_lo_base = xl_sb + (uint32_t)(a_r * 272 + a_kel * 2);
    int b_nloc = (lane & 7) + ((lane & 16) >> 1);
    int b_kel = (lane & 8);
    uint32_t b_rowoff = (uint32_t)((cblk * 64 + b_nloc) * 272 + b_kel * 2);

#pragma unroll
    for (int k = 0; k < 8; k++) {
        uint32_t ah[4], al[4];
        ldmx4(ah, a_hi_base + k * 32);
        ldmx4(al, a_lo_base + k * 32);
        uint32_t bh[4][4], bl[4][4];
#pragma unroll
        for (int nb2 = 0; nb2 < 4; nb2++) {
            uint32_t off = b_rowoff + (uint32_t)(nb2 * 16 * 272) + k * 32;
            ldmx4(bh[nb2], wh_sb + off);
            ldmx4(bl[nb2], wl_sb + off);
        }
#pragma unroll
        for (int nb = 0; nb < 8; nb++) {
            uint32_t b0h = bh[nb >> 1][(nb & 1) * 2], b1h = bh[nb >> 1][(nb & 1) * 2 + 1];
            uint32_t b0l = bl[nb >> 1][(nb & 1) * 2], b1l = bl[nb >> 1][(nb & 1) * 2 + 1];
            mma_bf16(acc[nb], ah, b0h, b1h);
            mma_bf16(acc[nb], al, b0h, b1h);
            mma_bf16(acc[nb], ah, b0l, b1l);
        }
    }

    int r0 = rowBase + rblk * 16 + g;
#pragma unroll
    for (int nb = 0; nb < 8; nb++) {
        int c = cblk * 64 + nb * 8 + 2 * tg;
        float bv0 = 0.f, bv1 = 0.f;
        if (bias) { bv0 = bias[c]; bv1 = bias[c + 1]; }
        if (r0 < M)
            *(float2*)&out[r0 * 128 + c] = make_float2(acc[nb][0] + bv0, acc[nb][1] + bv1);
        if (r0 + 8 < M)
            *(float2*)&out[(r0 + 8) * 128 + c] = make_float2(acc[nb][2] + bv0, acc[nb][3] + bv1);
    }
}

// ---------------- persistent fused edge MLP (mma.sync fp16, k16) ------------
#define ESM_US 0
#define ESM_WS 34816
#define ESM_B1 69632
#define ESM_W2 70144
#define ESM_PB 70656
#define ESM_BYTES 71680
#define N_TILES (N_EDGES / 128)
#define EDGE_GRID 296

__global__ void __launch_bounds__(256, 2) k_edge_mlp_fp16(
    const int* __restrict__ row, const int* __restrict__ col,
    const float* __restrict__ W1, const float* __restrict__ b1,
    const float* __restrict__ w2, const float* __restrict__ b2,
    float* __restrict__ out) {
    extern __shared__ char smc[];
    __half* Ws  = (__half*)(smc + ESM_WS);
    float* b1s  = (float*)(smc + ESM_B1);
    float* w2s  = (float*)(smc + ESM_W2);
    float* pbuf = (float*)(smc + ESM_PB);

    int tid = threadIdx.x;
    int lane = tid & 31, wid = tid >> 5;

#pragma unroll 4
    for (int it = 0; it < 64; it++) {
        int i = it * 256 + tid;
        int kk = i >> 7, n = i & 127;
        Ws[n * 136 + kk] = __float2half_rn(W1[i]);
    }
    if (tid < 128) { b1s[tid] = b1[tid]; w2s[tid] = w2[tid]; }
    float b2v = b2[0];
    __syncthreads();

    int rblk = wid >> 1, cblk = wid & 1;
    int g = lane >> 2, tg = lane & 3;

    uint32_t us_sb = (uint32_t)__cvta_generic_to_shared(smc + ESM_US);
    uint32_t ws_sb = (uint32_t)__cvta_generic_to_shared(smc + ESM_WS);
    uint32_t a_base = us_sb +
        (uint32_t)((rblk * 32 + (lane & 7) + (lane & 8)) * 272 + ((lane & 16) ? 16 : 0));
    uint32_t b_base = ws_sb +
        (uint32_t)((cblk * 64 + (lane & 7) + ((lane & 16) >> 1)) * 272 + (lane & 8) * 2);

    const float4* A4 = (const float4*)g_A;
    const float4* B4 = (const float4*)g_B;

    for (int tile = blockIdx.x; tile < N_TILES; tile += EDGE_GRID) {
        int e0 = tile * 128;

        {
            int i = tid >> 1, h = tid & 1;
            int r = row[e0 + i] * 32, c = col[e0 + i] * 32;
            __half2* dst = (__half2*)(smc + ESM_US + i * 272 + h * 128);
#pragma unroll
            for (int q = 0; q < 16; q++) {
                float4 a = A4[r + h * 16 + q];
                float4 b = B4[c + h * 16 + q];
                dst[q * 2 + 0] = __floats2half2_rn(fmaxf(a.x + b.x, 0.f),
                                                   fmaxf(a.y + b.y, 0.f));
                dst[q * 2 + 1] = __floats2half2_rn(fmaxf(a.z + b.z, 0.f),
                                                   fmaxf(a.w + b.w, 0.f));
            }
        }
        __syncthreads();

        float acc[2][8][4];
#pragma unroll
        for (int mt = 0; mt < 2; mt++)
#pragma unroll
            for (int n = 0; n < 8; n++)
#pragma unroll
                for (int j = 0; j < 4; j++) acc[mt][n][j] = 0.f;

#pragma unroll
        for (int k = 0; k < 8; k++) {
            uint32_t a0[4], a1[4];
            ldmx4(a0, a_base + k * 32);
            ldmx4(a1, a_base + 16 * 272 + k * 32);
            uint32_t bf[4][4];
#pragma unroll
            for (int nb2 = 0; nb2 < 4; nb2++)
                ldmx4(bf[nb2], b_base + (uint32_t)(nb2 * 16 * 272) + k * 32);
#pragma unroll
            for (int nb = 0; nb < 8; nb++) {
                uint32_t bb0 = bf[nb >> 1][(nb & 1) * 2];
                uint32_t bb1 = bf[nb >> 1][(nb & 1) * 2 + 1];
                mma_fp16(acc[0][nb], a0, bb0, bb1);
                mma_fp16(acc[1][nb], a1, bb0, bb1);
            }
        }

#pragma unroll
        for (int mt = 0; mt < 2; mt++) {
            float p0 = 0.f, p1 = 0.f;
#pragma unroll
            for (int nb = 0; nb < 8; nb++) {
                int c0 = cblk * 64 + nb * 8 + 2 * tg;
                float wv0 = w2s[c0], wv1 = w2s[c0 + 1];
                float bb0 = b1s[c0], bb1 = b1s[c0 + 1];
                p0 += fmaxf(acc[mt][nb][0] + bb0, 0.f) * wv0 + fmaxf(acc[mt][nb][1] + bb1, 0.f) * wv1;
                p1 += fmaxf(acc[mt][nb][2] + bb0, 0.f) * wv0 + fmaxf(acc[mt][nb][3] + bb1, 0.f) * wv1;
            }
            p0 += __shfl_xor_sync(0xffffffffu, p0, 1);
            p0 += __shfl_xor_sync(0xffffffffu, p0, 2);
            p1 += __shfl_xor_sync(0xffffffffu, p1, 1);
            p1 += __shfl_xor_sync(0xffffffffu, p1, 2);
            if (tg == 0) {
                int rr = rblk * 32 + mt * 16 + g;
                pbuf[cblk * 128 + rr] = p0;
                pbuf[cblk * 128 + rr + 8] = p1;
            }
        }
        __syncthreads();
        if (tid < 128) out[e0 + tid] = pbuf[tid] + pbuf[128 + tid] + b2v;
        __syncthreads();
    }
}

// ---------------- launch -----------------------------------------------------
extern "C" void kernel_launch(void* const* d_in, const int* in_sizes, int n_in,
                              void* d_out, int out_size) {
    const float* x       = (const float*)d_in[0];
    const int*   ei      = (const int*)d_in[1];
    const float* convs_W = (const float*)d_in[2];
    const float* convs_b = (const float*)d_in[3];
    const float* fc0_W   = (const float*)d_in[4];
    const float* fc0_b   = (const float*)d_in[5];
    const float* fc1_W   = (const float*)d_in[6];
    const float* fc1_b   = (const float*)d_in[7];
    const float* fc2_W   = (const float*)d_in[8];
    const float* fc2_b   = (const float*)d_in[9];
    float* out = (float*)d_out;

    const int* row = ei;
    const int* col = ei + N_EDGES;

    cudaFuncSetAttribute(k_gcn_layer, cudaFuncAttributeMaxDynamicSharedMemorySize, SGT_BYTES);
    cudaFuncSetAttribute(k_sgemm_tc, cudaFuncAttributeMaxDynamicSharedMemorySize, SGT_BYTES);
    cudaFuncSetAttribute(k_edge_mlp_fp16, cudaFuncAttributeMaxDynamicSharedMemorySize, ESM_BYTES);

    const int GRID_GEMM = (N_NODES + 63) / 64;

    // 1. setup: CSR + weight splits + x -> fp16 table buffer 0
    k_split_w<<<(10 * 16384 + 255) / 256, 256>>>(convs_W, fc0_W);
    k_zero_deg<<<(N_NODES + 255) / 256, 256>>>();
    k_count_deg<<<(N_EDGES + 255) / 256, 256>>>(col);
    k_cvt_x<<<(N_NODES * CDIM / 2 + 255) / 256, 256>>>(x);
    k_scan_dis<<<1, 1024>>>();
    k_fill_csr<<<(N_EDGES + 255) / 256, 256>>>(row, col);

    // 2. fused GCN layers, ping-ponging fp16 table: read l&1, write (l+1)&1
    for (int l = 0; l < N_LAYERS; l++)
        k_gcn_layer<<<GRID_GEMM, 256, SGT_BYTES>>>(l, convs_b + l * CDIM, l > 0, l & 1);

    // 3. factorized fc0: A = h@W0a + b0, B = h@W0b
    k_sgemm_tc<<<GRID_GEMM, 256, SGT_BYTES>>>(1, 8, fc0_b, N_NODES);
    k_sgemm_tc<<<GRID_GEMM, 256, SGT_BYTES>>>(2, 9, nullptr, N_NODES);

    // 4. persistent fused edge MLP (fp16 tensor cores)
    k_edge_mlp_fp16<<<EDGE_GRID, 256, ESM_BYTES>>>(row, col, fc1_W, fc1_b,
                                                   fc2_W, fc2_b, out);
}

// round 12
// speedup vs baseline: 1.2948x; 1.2948x over previous
#include <cuda_runtime.h>
#include <cuda_bf16.h>
#include <cuda_fp16.h>
#include <cstdint>

#define N_NODES 50000
#define N_EDGES 1600000
#define CDIM 128
#define N_LAYERS 8

// ---------------- scratch (device globals; no allocation allowed) ----------
__device__ float  g_h [N_NODES * CDIM];    // fp32 node features (residual / fc0 input)
__device__ __half g_hwh[N_NODES * CDIM];   // fp16 transformed features (gather table)
__device__ float  g_A [N_NODES * CDIM];
__device__ float  g_B [N_NODES * CDIM];
__device__ float  g_dis[N_NODES];
__device__ int    g_deg[N_NODES];
__device__ int    g_indptr[N_NODES + 1];
__device__ int    g_cursor[N_NODES];
__device__ int    g_csr_src[N_EDGES];
__device__ float  g_csr_nrm[N_EDGES];
// transposed + bf16 hi/lo-split weights for node GEMMs: [10][n=128][k=128]
__device__ __nv_bfloat16 g_Wth[10 * 128 * 128];
__device__ __nv_bfloat16 g_Wtl[10 * 128 * 128];

// ---------------- helpers ----------------------------------------------------
__device__ __forceinline__ void mma_bf16(float d[4], const uint32_t a[4],
                                         uint32_t b0, uint32_t b1) {
    asm volatile(
        "mma.sync.aligned.m16n8k16.row.col.f32.bf16.bf16.f32 "
        "{%0,%1,%2,%3}, {%4,%5,%6,%7}, {%8,%9}, {%0,%1,%2,%3};"
        : "+f"(d[0]), "+f"(d[1]), "+f"(d[2]), "+f"(d[3])
        : "r"(a[0]), "r"(a[1]), "r"(a[2]), "r"(a[3]), "r"(b0), "r"(b1));
}
__device__ __forceinline__ void mma_fp16(float d[4], const uint32_t a[4],
                                         uint32_t b0, uint32_t b1) {
    asm volatile(
        "mma.sync.aligned.m16n8k16.row.col.f32.f16.f16.f32 "
        "{%0,%1,%2,%3}, {%4,%5,%6,%7}, {%8,%9}, {%0,%1,%2,%3};"
        : "+f"(d[0]), "+f"(d[1]), "+f"(d[2]), "+f"(d[3])
        : "r"(a[0]), "r"(a[1]), "r"(a[2]), "r"(a[3]), "r"(b0), "r"(b1));
}
__device__ __forceinline__ void ldmx4(uint32_t r[4], uint32_t addr) {
    asm volatile("ldmatrix.sync.aligned.m8n8.x4.shared.b16 {%0,%1,%2,%3}, [%4];"
                 : "=r"(r[0]), "=r"(r[1]), "=r"(r[2]), "=r"(r[3]) : "r"(addr));
}
__device__ __forceinline__ float4 f4add(float4 a, float4 b) {
    return make_float4(a.x + b.x, a.y + b.y, a.z + b.z, a.w + b.w);
}
__device__ __forceinline__ float4 f4relu(float4 a) {
    return make_float4(fmaxf(a.x, 0.f), fmaxf(a.y, 0.f), fmaxf(a.z, 0.f), fmaxf(a.w, 0.f));
}
__device__ __forceinline__ uint32_t pack_bf16(float a, float b) {
    uint32_t lo = (uint32_t)__bfloat16_as_ushort(__float2bfloat16(a));
    uint32_t hi = (uint32_t)__bfloat16_as_ushort(__float2bfloat16(b));
    return lo | (hi << 16);
}
// accumulate 8 fp16 channels (uint4) scaled by nr into two float4s
__device__ __forceinline__ void acc_h8(float4& a0, float4& a1, uint4 raw, float nr) {
    __half2 h0 = *(__half2*)&raw.x;
    __half2 h1 = *(__half2*)&raw.y;
    __half2 h2 = *(__half2*)&raw.z;
    __half2 h3 = *(__half2*)&raw.w;
    float2 f0 = __half22float2(h0);
    float2 f1 = __half22float2(h1);
    float2 f2 = __half22float2(h2);
    float2 f3 = __half22float2(h3);
    a0.x += nr * f0.x; a0.y += nr * f0.y;
    a0.z += nr * f1.x; a0.w += nr * f1.y;
    a1.x += nr * f2.x; a1.y += nr * f2.y;
    a1.z += nr * f3.x; a1.w += nr * f3.y;
}

// ---------------- setup kernels ---------------------------------------------
__global__ void k_zero_deg() {
    int i = blockIdx.x * blockDim.x + threadIdx.x;
    if (i < N_NODES) g_deg[i] = 0;
}

__global__ void k_count_deg(const int* __restrict__ col) {
    int e = blockIdx.x * blockDim.x + threadIdx.x;
    if (e < N_EDGES) atomicAdd(&g_deg[col[e]], 1);
}

__global__ void k_scan_dis() {
    __shared__ int sbuf[1024];
    __shared__ int s_carry;
    int t = threadIdx.x;
    if (t == 0) s_carry = 0;
    __syncthreads();
    for (int base = 0; base < N_NODES; base += 1024) {
        int idx = base + t;
        int v = (idx < N_NODES) ? g_deg[idx] : 0;
        sbuf[t] = v;
        __syncthreads();
        for (int off = 1; off < 1024; off <<= 1) {
            int y = (t >= off) ? sbuf[t - off] : 0;
            __syncthreads();
            sbuf[t] += y;
            __syncthreads();
        }
        int incl = sbuf[t];
        int carry = s_carry;
        if (idx < N_NODES) {
            int excl = carry + incl - v;
            g_indptr[idx] = excl;
            g_cursor[idx] = excl;
            g_dis[idx] = rsqrtf((float)(v + 1));
        }
        __syncthreads();
        if (t == 1023) s_carry = carry + sbuf[1023];
        __syncthreads();
    }
    if (t == 0) g_indptr[N_NODES] = s_carry;
}

__global__ void k_fill_csr(const int* __restrict__ row, const int* __restrict__ col) {
    int e = blockIdx.x * blockDim.x + threadIdx.x;
    if (e < N_EDGES) {
        int r = row[e], c = col[e];
        float nrm = g_dis[r] * g_dis[c];
        int pos = atomicAdd(&g_cursor[c], 1);
        g_csr_src[pos] = r;
        g_csr_nrm[pos] = nrm;
    }
}

// ---------------- W transpose + bf16 hi/lo split (once) ---------------------
__global__ void k_split_w(const float* __restrict__ convs_W,
                          const float* __restrict__ fc0_W) {
    int idx = blockIdx.x * 256 + threadIdx.x;
    if (idx >= 10 * 16384) return;
    int l = idx >> 14;
    int kk = (idx >> 7) & 127;
    int n = idx & 127;
    float v = (l < 8) ? convs_W[idx] : fc0_W[idx - 8 * 16384];
    __nv_bfloat16 hi = __float2bfloat16(v);
    float lo = v - __bfloat162float(hi);
    int dst = (l << 14) + (n << 7) + kk;
    g_Wth[dst] = hi;
    g_Wtl[dst] = __float2bfloat16(lo);
}

// ---------------- tensor-core node GEMM (bf16x2 3-pass, ~fp32 accurate) -----
// out[M,128] = Ain[M,128] @ W_l[128,128] (+bias). CTA: 64 rows, 256 thr/8 warps.
// out_sel==0 writes fp16 g_hwh (aggregation gather table); 1/2 -> fp32 A/B.
#define SGT_XH 0
#define SGT_XL 17408
#define SGT_WH 34816
#define SGT_WL 69632
#define SGT_BYTES 104448

__global__ void __launch_bounds__(256, 2) k_sgemm_tc(
    const float* __restrict__ Aext, int a_sel, int out_sel, int layer,
    const float* __restrict__ bias, int M) {
    extern __shared__ char smc[];
    const float* Ain = a_sel ? g_h : Aext;

    int tid = threadIdx.x;
    int lane = tid & 31, wid = tid >> 5;
    int rowBase = blockIdx.x * 64;

    // --- stage X split (64 x 128 fp32 -> hi/lo bf16, stride 136) ------------
    {
        const float4* A4 = (const float4*)Ain;
        uint32_t* Xh32 = (uint32_t*)(smc + SGT_XH);
        uint32_t* Xl32 = (uint32_t*)(smc + SGT_XL);
#pragma unroll
        for (int i = 0; i < 8; i++) {
            int idx = tid + i * 256;
            int rr = idx >> 5, c4 = idx & 31;
            float4 v = make_float4(0.f, 0.f, 0.f, 0.f);
            if (rowBase + rr < M) v = A4[(rowBase + rr) * 32 + c4];
            __nv_bfloat16 h0 = __float2bfloat16(v.x);
            __nv_bfloat16 h1 = __float2bfloat16(v.y);
            __nv_bfloat16 h2 = __float2bfloat16(v.z);
            __nv_bfloat16 h3 = __float2bfloat16(v.w);
            uint32_t hp0 = (uint32_t)__bfloat16_as_ushort(h0) |
                           ((uint32_t)__bfloat16_as_ushort(h1) << 16);
            uint32_t hp1 = (uint32_t)__bfloat16_as_ushort(h2) |
                           ((uint32_t)__bfloat16_as_ushort(h3) << 16);
            uint32_t lp0 = pack_bf16(v.x - __bfloat162float(h0), v.y - __bfloat162float(h1));
            uint32_t lp1 = pack_bf16(v.z - __bfloat162float(h2), v.w - __bfloat162float(h3));
            int o = rr * 68 + c4 * 2;
            *(uint2*)&Xh32[o] = make_uint2(hp0, hp1);
            *(uint2*)&Xl32[o] = make_uint2(lp0, lp1);
        }
    }
    // --- stage W hi/lo (pre-transposed [n][k]) -------------------------------
    {
        const uint4* Wh4 = (const uint4*)(g_Wth + layer * 16384);
        const uint4* Wl4 = (const uint4*)(g_Wtl + layer * 16384);
#pragma unroll
        for (int i = 0; i < 8; i++) {
            int idx = tid + i * 256;
            int rr = idx >> 4, c8 = idx & 15;
            *(uint4*)(smc + SGT_WH + rr * 272 + c8 * 16) = Wh4[rr * 16 + c8];
            *(uint4*)(smc + SGT_WL + rr * 272 + c8 * 16) = Wl4[rr * 16 + c8];
        }
    }
    __syncthreads();

    int g = lane >> 2, tg = lane & 3;
    int rblk = wid >> 1, cblk = wid & 1;

    float acc[8][4];
#pragma unroll
    for (int n = 0; n < 8; n++)
#pragma unroll
        for (int j = 0; j < 4; j++) acc[n][j] = 0.f;

    uint32_t xh_sb = (uint32_t)__cvta_generic_to_shared(smc + SGT_XH);
    uint32_t xl_sb = (uint32_t)__cvta_generic_to_shared(smc + SGT_XL);
    uint32_t wh_sb = (uint32_t)__cvta_generic_to_shared(smc + SGT_WH);
    uint32_t wl_sb = (uint32_t)__cvta_generic_to_shared(smc + SGT_WL);

    int a_r = rblk * 16 + (lane & 7) + (lane & 8);
    int a_kel = (lane & 16) ? 8 : 0;
    uint32_t a_hi_base = xh_sb + (uint32_t)(a_r * 272 + a_kel * 2);
    uint32_t a_lo_base = xl_sb + (uint32_t)(a_r * 272 + a_kel * 2);
    int b_nloc = (lane & 7) + ((lane & 16) >> 1);
    int b_kel = (lane & 8);
    uint32_t b_rowoff = (uint32_t)((cblk * 64 + b_nloc) * 272 + b_kel * 2);

#pragma unroll
    for (int k = 0; k < 8; k++) {
        uint32_t ah[4], al[4];
        ldmx4(ah, a_hi_base + k * 32);
        ldmx4(al, a_lo_base + k * 32);
        uint32_t bh[4][4], bl[4][4];
#pragma unroll
        for (int nb2 = 0; nb2 < 4; nb2++) {
            uint32_t off = b_rowoff + (uint32_t)(nb2 * 16 * 272) + k * 32;
            ldmx4(bh[nb2], wh_sb + off);
            ldmx4(bl[nb2], wl_sb + off);
        }
#pragma unroll
        for (int nb = 0; nb < 8; nb++) {
            uint32_t b0h = bh[nb >> 1][(nb & 1) * 2], b1h = bh[nb >> 1][(nb & 1) * 2 + 1];
            uint32_t b0l = bl[nb >> 1][(nb & 1) * 2], b1l = bl[nb >> 1][(nb & 1) * 2 + 1];
            mma_bf16(acc[nb], ah, b0h, b1h);
            mma_bf16(acc[nb], al, b0h, b1h);
            mma_bf16(acc[nb], ah, b0l, b1l);
        }
    }

    // --- epilogue -------------------------------------------------------------
    int r0 = rowBase + rblk * 16 + g;
    if (out_sel == 0) {
        __half2* oh = (__half2*)g_hwh;
#pragma unroll
        for (int nb = 0; nb < 8; nb++) {
            int c = cblk * 64 + nb * 8 + 2 * tg;
            if (r0 < M)
                oh[(r0 * 128 + c) >> 1] = __floats2half2_rn(acc[nb][0], acc[nb][1]);
            if (r0 + 8 < M)
                oh[((r0 + 8) * 128 + c) >> 1] = __floats2half2_rn(acc[nb][2], acc[nb][3]);
        }
    } else {
        float* out = (out_sel == 1) ? g_A : g_B;
#pragma unroll
        for (int nb = 0; nb < 8; nb++) {
            int c = cblk * 64 + nb * 8 + 2 * tg;
            float bv0 = 0.f, bv1 = 0.f;
            if (bias) { bv0 = bias[c]; bv1 = bias[c + 1]; }
            if (r0 < M)
                *(float2*)&out[r0 * 128 + c] = make_float2(acc[nb][0] + bv0, acc[nb][1] + bv1);
            if (r0 + 8 < M)
                *(float2*)&out[(r0 + 8) * 128 + c] = make_float2(acc[nb][2] + bv0, acc[nb][3] + bv1);
        }
    }
}

// ---------------- aggregation: h[n] = relu(self + sum + bias (+res)) --------
// 2 nodes per warp, 16 lanes per node, uint4 (8 fp16 ch) per lane.
// Same per-channel edge order as before -> identical numerics.
__global__ void k_agg(const float* __restrict__ bias, int residual) {
    int gw = (blockIdx.x * blockDim.x + threadIdx.x) >> 5;   // warp id
    int lane = threadIdx.x & 31;
    int half = lane >> 4, hl = lane & 15;                     // node-in-warp, lane-in-node
    int n = gw * 2 + half;
    if (n >= N_NODES) return;

    const uint4* hw4 = (const uint4*)g_hwh;   // 8 fp16 channels per uint4; 16 per row
    float d = g_dis[n];
    float ds = d * d;
    float4 acc0 = make_float4(0.f, 0.f, 0.f, 0.f);
    float4 acc1 = make_float4(0.f, 0.f, 0.f, 0.f);
    acc_h8(acc0, acc1, hw4[n * 16 + hl], ds);   // self term

    int e = g_indptr[n];
    int end = g_indptr[n + 1];
    for (; e + 8 <= end; e += 8) {
        int s[8]; float nr[8]; uint4 v[8];
#pragma unroll
        for (int j = 0; j < 8; j++) { s[j] = g_csr_src[e + j]; nr[j] = g_csr_nrm[e + j]; }
#pragma unroll
        for (int j = 0; j < 8; j++) v[j] = hw4[s[j] * 16 + hl];
#pragma unroll
        for (int j = 0; j < 8; j++) acc_h8(acc0, acc1, v[j], nr[j]);
    }
    if (e + 4 <= end) {
        int s[4]; float nr[4]; uint4 v[4];
#pragma unroll
        for (int j = 0; j < 4; j++) { s[j] = g_csr_src[e + j]; nr[j] = g_csr_nrm[e + j]; }
#pragma unroll
        for (int j = 0; j < 4; j++) v[j] = hw4[s[j] * 16 + hl];
#pragma unroll
        for (int j = 0; j < 4; j++) acc_h8(acc0, acc1, v[j], nr[j]);
        e += 4;
    }
    for (; e < end; e++)
        acc_h8(acc0, acc1, hw4[g_csr_src[e] * 16 + hl], g_csr_nrm[e]);

    float4 b0 = ((const float4*)bias)[hl * 2];
    float4 b1 = ((const float4*)bias)[hl * 2 + 1];
    acc0 = f4add(acc0, b0);
    acc1 = f4add(acc1, b1);
    if (residual) {
        acc0 = f4add(acc0, ((const float4*)g_h)[n * 32 + hl * 2]);
        acc1 = f4add(acc1, ((const float4*)g_h)[n * 32 + hl * 2 + 1]);
    }
    ((float4*)g_h)[n * 32 + hl * 2] = f4relu(acc0);
    ((float4*)g_h)[n * 32 + hl * 2 + 1] = f4relu(acc1);
}

// ---------------- persistent fused edge MLP (mma.sync fp16, k16) ------------
#define ESM_US 0
#define ESM_WS 34816
#define ESM_B1 69632
#define ESM_W2 70144
#define ESM_PB 70656
#define ESM_BYTES 71680
#define N_TILES (N_EDGES / 128)
#define EDGE_GRID 296

__global__ void __launch_bounds__(256, 2) k_edge_mlp_fp16(
    const int* __restrict__ row, const int* __restrict__ col,
    const float* __restrict__ W1, const float* __restrict__ b1,
    const float* __restrict__ w2, const float* __restrict__ b2,
    float* __restrict__ out) {
    extern __shared__ char smc[];
    __half* Ws  = (__half*)(smc + ESM_WS);
    float* b1s  = (float*)(smc + ESM_B1);
    float* w2s  = (float*)(smc + ESM_W2);
    float* pbuf = (float*)(smc + ESM_PB);

    int tid = threadIdx.x;
    int lane = tid & 31, wid = tid >> 5;

#pragma unroll 4
    for (int it = 0; it < 64; it++) {
        int i = it * 256 + tid;
        int kk = i >> 7, n = i & 127;
        Ws[n * 136 + kk] = __float2half_rn(W1[i]);
    }
    if (tid < 128) { b1s[tid] = b1[tid]; w2s[tid] = w2[tid]; }
    float b2v = b2[0];
    __syncthreads();

    int rblk = wid >> 1, cblk = wid & 1;
    int g = lane >> 2, tg = lane & 3;

    uint32_t us_sb = (uint32_t)__cvta_generic_to_shared(smc + ESM_US);
    uint32_t ws_sb = (uint32_t)__cvta_generic_to_shared(smc + ESM_WS);
    uint32_t a_base = us_sb +
        (uint32_t)((rblk * 32 + (lane & 7) + (lane & 8)) * 272 + ((lane & 16) ? 16 : 0));
    uint32_t b_base = ws_sb +
        (uint32_t)((cblk * 64 + (lane & 7) + ((lane & 16) >> 1)) * 272 + (lane & 8) * 2);

    const float4* A4 = (const float4*)g_A;
    const float4* B4 = (const float4*)g_B;

    for (int tile = blockIdx.x; tile < N_TILES; tile += EDGE_GRID) {
        int e0 = tile * 128;

        {
            int i = tid >> 1, h = tid & 1;
            int r = row[e0 + i] * 32, c = col[e0 + i] * 32;
            __half2* dst = (__half2*)(smc + ESM_US + i * 272 + h * 128);
#pragma unroll
            for (int q = 0; q < 16; q++) {
                float4 a = A4[r + h * 16 + q];
                float4 b = B4[c + h * 16 + q];
                dst[q * 2 + 0] = __floats2half2_rn(fmaxf(a.x + b.x, 0.f),
                                                   fmaxf(a.y + b.y, 0.f));
                dst[q * 2 + 1] = __floats2half2_rn(fmaxf(a.z + b.z, 0.f),
                                                   fmaxf(a.w + b.w, 0.f));
            }
        }
        __syncthreads();

        float acc[2][8][4];
#pragma unroll
        for (int mt = 0; mt < 2; mt++)
#pragma unroll
            for (int n = 0; n < 8; n++)
#pragma unroll
                for (int j = 0; j < 4; j++) acc[mt][n][j] = 0.f;

#pragma unroll
        for (int k = 0; k < 8; k++) {
            uint32_t a0[4], a1[4];
            ldmx4(a0, a_base + k * 32);
            ldmx4(a1, a_base + 16 * 272 + k * 32);
            uint32_t bf[4][4];
#pragma unroll
            for (int nb2 = 0; nb2 < 4; nb2++)
                ldmx4(bf[nb2], b_base + (uint32_t)(nb2 * 16 * 272) + k * 32);
#pragma unroll
            for (int nb = 0; nb < 8; nb++) {
                uint32_t bb0 = bf[nb >> 1][(nb & 1) * 2];
                uint32_t bb1 = bf[nb >> 1][(nb & 1) * 2 + 1];
                mma_fp16(acc[0][nb], a0, bb0, bb1);
                mma_fp16(acc[1][nb], a1, bb0, bb1);
            }
        }

#pragma unroll
        for (int mt = 0; mt < 2; mt++) {
            float p0 = 0.f, p1 = 0.f;
#pragma unroll
            for (int nb = 0; nb < 8; nb++) {
                int c0 = cblk * 64 + nb * 8 + 2 * tg;
                float wv0 = w2s[c0], wv1 = w2s[c0 + 1];
                float bb0 = b1s[c0], bb1 = b1s[c0 + 1];
                p0 += fmaxf(acc[mt][nb][0] + bb0, 0.f) * wv0 + fmaxf(acc[mt][nb][1] + bb1, 0.f) * wv1;
                p1 += fmaxf(acc[mt][nb][2] + bb0, 0.f) * wv0 + fmaxf(acc[mt][nb][3] + bb1, 0.f) * wv1;
            }
            p0 += __shfl_xor_sync(0xffffffffu, p0, 1);
            p0 += __shfl_xor_sync(0xffffffffu, p0, 2);
            p1 += __shfl_xor_sync(0xffffffffu, p1, 1);
            p1 += __shfl_xor_sync(0xffffffffu, p1, 2);
            if (tg == 0) {
                int rr = rblk * 32 + mt * 16 + g;
                pbuf[cblk * 128 + rr] = p0;
                pbuf[cblk * 128 + rr + 8] = p1;
            }
        }
        __syncthreads();
        if (tid < 128) out[e0 + tid] = pbuf[tid] + pbuf[128 + tid] + b2v;
        __syncthreads();
    }
}

// ---------------- launch -----------------------------------------------------
extern "C" void kernel_launch(void* const* d_in, const int* in_sizes, int n_in,
                              void* d_out, int out_size) {
    const float* x       = (const float*)d_in[0];
    const int*   ei      = (const int*)d_in[1];
    const float* convs_W = (const float*)d_in[2];
    const float* convs_b = (const float*)d_in[3];
    const float* fc0_W   = (const float*)d_in[4];
    const float* fc0_b   = (const float*)d_in[5];
    const float* fc1_W   = (const float*)d_in[6];
    const float* fc1_b   = (const float*)d_in[7];
    const float* fc2_W   = (const float*)d_in[8];
    const float* fc2_b   = (const float*)d_in[9];
    float* out = (float*)d_out;

    const int* row = ei;
    const int* col = ei + N_EDGES;

    cudaFuncSetAttribute(k_sgemm_tc, cudaFuncAttributeMaxDynamicSharedMemorySize, SGT_BYTES);
    cudaFuncSetAttribute(k_edge_mlp_fp16, cudaFuncAttributeMaxDynamicSharedMemorySize, ESM_BYTES);

    const int GRID_GEMM = (N_NODES + 63) / 64;
    const int GRID_AGG  = (N_NODES * 16 + 255) / 256;   // 2 nodes per warp

    // 1. setup (sgemm L0 in the profiled 4th slot)
    k_split_w<<<(10 * 16384 + 255) / 256, 256>>>(convs_W, fc0_W);
    k_zero_deg<<<(N_NODES + 255) / 256, 256>>>();
    k_count_deg<<<(N_EDGES + 255) / 256, 256>>>(col);
    k_sgemm_tc<<<GRID_GEMM, 256, SGT_BYTES>>>(x, 0, 0, 0, nullptr, N_NODES);   // L0 GEMM
    k_scan_dis<<<1, 1024>>>();
    k_fill_csr<<<(N_EDGES + 255) / 256, 256>>>(row, col);
    k_agg<<<GRID_AGG, 256>>>(convs_b, 0);                                      // L0 agg

    // 2. GCN layers 1..7
    for (int l = 1; l < N_LAYERS; l++) {
        k_sgemm_tc<<<GRID_GEMM, 256, SGT_BYTES>>>(x, 1, 0, l, nullptr, N_NODES);
        k_agg<<<GRID_AGG, 256>>>(convs_b + l * CDIM, 1);
    }

    // 3. factorized fc0: A = h@W0a + b0, B = h@W0b
    k_sgemm_tc<<<GRID_GEMM, 256, SGT_BYTES>>>(nullptr, 1, 1, 8, fc0_b, N_NODES);
    k_sgemm_tc<<<GRID_GEMM, 256, SGT_BYTES>>>(nullptr, 1, 2, 9, nullptr, N_NODES);

    // 4. persistent fused edge MLP (fp16 tensor cores)
    k_edge_mlp_fp16<<<EDGE_GRID, 256, ESM_BYTES>>>(row, col, fc1_W, fc1_b,
                                                   fc2_W, fc2_b, out);
}

// round 13
// speedup vs baseline: 1.3844x; 1.0692x over previous
#include <cuda_runtime.h>
#include <cuda_bf16.h>
#include <cuda_fp16.h>
#include <cstdint>

#define N_NODES 50000
#define N_EDGES 1600000
#define CDIM 128
#define N_LAYERS 8

// ---------------- scratch (device globals; no allocation allowed) ----------
__device__ float  g_h [N_NODES * CDIM];    // fp32 node features (residual / fc0 input)
__device__ __half g_hwh[N_NODES * CDIM];   // fp16 transformed features (gather table)
__device__ float  g_A [N_NODES * CDIM];
__device__ float  g_B [N_NODES * CDIM];
__device__ float  g_dis[N_NODES];
__device__ int    g_deg[N_NODES];
__device__ int    g_indptr[N_NODES + 1];
__device__ int    g_cursor[N_NODES];
__device__ int    g_csr_src[N_EDGES];
__device__ int    g_csr_dst[N_EDGES];
__device__ int    g_csr_eid[N_EDGES];
__device__ float  g_csr_nrm[N_EDGES];
// transposed + bf16 hi/lo-split weights for node GEMMs: [10][n=128][k=128]
__device__ __nv_bfloat16 g_Wth[10 * 128 * 128];
__device__ __nv_bfloat16 g_Wtl[10 * 128 * 128];

// ---------------- helpers ----------------------------------------------------
__device__ __forceinline__ void mma_bf16(float d[4], const uint32_t a[4],
                                         uint32_t b0, uint32_t b1) {
    asm volatile(
        "mma.sync.aligned.m16n8k16.row.col.f32.bf16.bf16.f32 "
        "{%0,%1,%2,%3}, {%4,%5,%6,%7}, {%8,%9}, {%0,%1,%2,%3};"
        : "+f"(d[0]), "+f"(d[1]), "+f"(d[2]), "+f"(d[3])
        : "r"(a[0]), "r"(a[1]), "r"(a[2]), "r"(a[3]), "r"(b0), "r"(b1));
}
__device__ __forceinline__ void mma_fp16(float d[4], const uint32_t a[4],
                                         uint32_t b0, uint32_t b1) {
    asm volatile(
        "mma.sync.aligned.m16n8k16.row.col.f32.f16.f16.f32 "
        "{%0,%1,%2,%3}, {%4,%5,%6,%7}, {%8,%9}, {%0,%1,%2,%3};"
        : "+f"(d[0]), "+f"(d[1]), "+f"(d[2]), "+f"(d[3])
        : "r"(a[0]), "r"(a[1]), "r"(a[2]), "r"(a[3]), "r"(b0), "r"(b1));
}
__device__ __forceinline__ void ldmx4(uint32_t r[4], uint32_t addr) {
    asm volatile("ldmatrix.sync.aligned.m8n8.x4.shared.b16 {%0,%1,%2,%3}, [%4];"
                 : "=r"(r[0]), "=r"(r[1]), "=r"(r[2]), "=r"(r[3]) : "r"(addr));
}
__device__ __forceinline__ float4 f4add(float4 a, float4 b) {
    return make_float4(a.x + b.x, a.y + b.y, a.z + b.z, a.w + b.w);
}
__device__ __forceinline__ float4 f4relu(float4 a) {
    return make_float4(fmaxf(a.x, 0.f), fmaxf(a.y, 0.f), fmaxf(a.z, 0.f), fmaxf(a.w, 0.f));
}
__device__ __forceinline__ uint32_t pack_bf16(float a, float b) {
    uint32_t lo = (uint32_t)__bfloat16_as_ushort(__float2bfloat16(a));
    uint32_t hi = (uint32_t)__bfloat16_as_ushort(__float2bfloat16(b));
    return lo | (hi << 16);
}
// accumulate 8 fp16 channels (uint4) scaled by nr into two float4s
__device__ __forceinline__ void acc_h8(float4& a0, float4& a1, uint4 raw, float nr) {
    __half2 h0 = *(__half2*)&raw.x;
    __half2 h1 = *(__half2*)&raw.y;
    __half2 h2 = *(__half2*)&raw.z;
    __half2 h3 = *(__half2*)&raw.w;
    float2 f0 = __half22float2(h0);
    float2 f1 = __half22float2(h1);
    float2 f2 = __half22float2(h2);
    float2 f3 = __half22float2(h3);
    a0.x += nr * f0.x; a0.y += nr * f0.y;
    a0.z += nr * f1.x; a0.w += nr * f1.y;
    a1.x += nr * f2.x; a1.y += nr * f2.y;
    a1.z += nr * f3.x; a1.w += nr * f3.y;
}

// ---------------- setup kernels ---------------------------------------------
__global__ void k_zero_deg() {
    int i = blockIdx.x * blockDim.x + threadIdx.x;
    if (i < N_NODES) g_deg[i] = 0;
}

__global__ void k_count_deg(const int* __restrict__ col) {
    int e = blockIdx.x * blockDim.x + threadIdx.x;
    if (e < N_EDGES) atomicAdd(&g_deg[col[e]], 1);
}

__global__ void k_scan_dis() {
    __shared__ int sbuf[1024];
    __shared__ int s_carry;
    int t = threadIdx.x;
    if (t == 0) s_carry = 0;
    __syncthreads();
    for (int base = 0; base < N_NODES; base += 1024) {
        int idx = base + t;
        int v = (idx < N_NODES) ? g_deg[idx] : 0;
        sbuf[t] = v;
        __syncthreads();
        for (int off = 1; off < 1024; off <<= 1) {
            int y = (t >= off) ? sbuf[t - off] : 0;
            __syncthreads();
            sbuf[t] += y;
            __syncthreads();
        }
        int incl = sbuf[t];
        int carry = s_carry;
        if (idx < N_NODES) {
            int excl = carry + incl - v;
            g_indptr[idx] = excl;
            g_cursor[idx] = excl;
            g_dis[idx] = rsqrtf((float)(v + 1));
        }
        __syncthreads();
        if (t == 1023) s_carry = carry + sbuf[1023];
        __syncthreads();
    }
    if (t == 0) g_indptr[N_NODES] = s_carry;
}

__global__ void k_fill_csr(const int* __restrict__ row, const int* __restrict__ col) {
    int e = blockIdx.x * blockDim.x + threadIdx.x;
    if (e < N_EDGES) {
        int r = row[e], c = col[e];
        float nrm = g_dis[r] * g_dis[c];
        int pos = atomicAdd(&g_cursor[c], 1);
        g_csr_src[pos] = r;
        g_csr_dst[pos] = c;
        g_csr_eid[pos] = e;
        g_csr_nrm[pos] = nrm;
    }
}

// ---------------- W transpose + bf16 hi/lo split (once) ---------------------
__global__ void k_split_w(const float* __restrict__ convs_W,
                          const float* __restrict__ fc0_W) {
    int idx = blockIdx.x * 256 + threadIdx.x;
    if (idx >= 10 * 16384) return;
    int l = idx >> 14;
    int kk = (idx >> 7) & 127;
    int n = idx & 127;
    float v = (l < 8) ? convs_W[idx] : fc0_W[idx - 8 * 16384];
    __nv_bfloat16 hi = __float2bfloat16(v);
    float lo = v - __bfloat162float(hi);
    int dst = (l << 14) + (n << 7) + kk;
    g_Wth[dst] = hi;
    g_Wtl[dst] = __float2bfloat16(lo);
}

// ---------------- tensor-core node GEMM (bf16x2 3-pass, ~fp32 accurate) -----
// out[M,128] = Ain[M,128] @ W_l[128,128] (+bias). CTA: 64 rows, 256 thr/8 warps.
// out_sel==0 writes fp16 g_hwh (aggregation gather table); 1/2 -> fp32 A/B.
#define SGT_XH 0
#define SGT_XL 17408
#define SGT_WH 34816
#define SGT_WL 69632
#define SGT_BYTES 104448

__global__ void __launch_bounds__(256, 2) k_sgemm_tc(
    const float* __restrict__ Aext, int a_sel, int out_sel, int layer,
    const float* __restrict__ bias, int M) {
    extern __shared__ char smc[];
    const float* Ain = a_sel ? g_h : Aext;

    int tid = threadIdx.x;
    int lane = tid & 31, wid = tid >> 5;
    int rowBase = blockIdx.x * 64;

    // --- stage X split (64 x 128 fp32 -> hi/lo bf16, stride 136) ------------
    {
        const float4* A4 = (const float4*)Ain;
        uint32_t* Xh32 = (uint32_t*)(smc + SGT_XH);
        uint32_t* Xl32 = (uint32_t*)(smc + SGT_XL);
#pragma unroll
        for (int i = 0; i < 8; i++) {
            int idx = tid + i * 256;
            int rr = idx >> 5, c4 = idx & 31;
            float4 v = make_float4(0.f, 0.f, 0.f, 0.f);
            if (rowBase + rr < M) v = A4[(rowBase + rr) * 32 + c4];
            __nv_bfloat16 h0 = __float2bfloat16(v.x);
            __nv_bfloat16 h1 = __float2bfloat16(v.y);
            __nv_bfloat16 h2 = __float2bfloat16(v.z);
            __nv_bfloat16 h3 = __float2bfloat16(v.w);
            uint32_t hp0 = (uint32_t)__bfloat16_as_ushort(h0) |
                           ((uint32_t)__bfloat16_as_ushort(h1) << 16);
            uint32_t hp1 = (uint32_t)__bfloat16_as_ushort(h2) |
                           ((uint32_t)__bfloat16_as_ushort(h3) << 16);
            uint32_t lp0 = pack_bf16(v.x - __bfloat162float(h0), v.y - __bfloat162float(h1));
            uint32_t lp1 = pack_bf16(v.z - __bfloat162float(h2), v.w - __bfloat162float(h3));
            int o = rr * 68 + c4 * 2;
            *(uint2*)&Xh32[o] = make_uint2(hp0, hp1);
            *(uint2*)&Xl32[o] = make_uint2(lp0, lp1);
        }
    }
    // --- stage W hi/lo (pre-transposed [n][k]) -------------------------------
    {
        const uint4* Wh4 = (const uint4*)(g_Wth + layer * 16384);
        const uint4* Wl4 = (const uint4*)(g_Wtl + layer * 16384);
#pragma unroll
        for (int i = 0; i < 8; i++) {
            int idx = tid + i * 256;
            int rr = idx >> 4, c8 = idx & 15;
            *(uint4*)(smc + SGT_WH + rr * 272 + c8 * 16) = Wh4[rr * 16 + c8];
            *(uint4*)(smc + SGT_WL + rr * 272 + c8 * 16) = Wl4[rr * 16 + c8];
        }
    }
    __syncthreads();

    int g = lane >> 2, tg = lane & 3;
    int rblk = wid >> 1, cblk = wid & 1;

    float acc[8][4];
#pragma unroll
    for (int n = 0; n < 8; n++)
#pragma unroll
        for (int j = 0; j < 4; j++) acc[n][j] = 0.f;

    uint32_t xh_sb = (uint32_t)__cvta_generic_to_shared(smc + SGT_XH);
    uint32_t xl_sb = (uint32_t)__cvta_generic_to_shared(smc + SGT_XL);
    uint32_t wh_sb = (uint32_t)__cvta_generic_to_shared(smc + SGT_WH);
    uint32_t wl_sb = (uint32_t)__cvta_generic_to_shared(smc + SGT_WL);

    int a_r = rblk * 16 + (lane & 7) + (lane & 8);
    int a_kel = (lane & 16) ? 8 : 0;
    uint32_t a_hi_base = xh_sb + (uint32_t)(a_r * 272 + a_kel * 2);
    uint32_t a_lo_base = xl_sb + (uint32_t)(a_r * 272 + a_kel * 2);
    int b_nloc = (lane & 7) + ((lane & 16) >> 1);
    int b_kel = (lane & 8);
    uint32_t b_rowoff = (uint32_t)((cblk * 64 + b_nloc) * 272 + b_kel * 2);

#pragma unroll
    for (int k = 0; k < 8; k++) {
        uint32_t ah[4], al[4];
        ldmx4(ah, a_hi_base + k * 32);
        ldmx4(al, a_lo_base + k * 32);
        uint32_t bh[4][4], bl[4][4];
#pragma unroll
        for (int nb2 = 0; nb2 < 4; nb2++) {
            uint32_t off = b_rowoff + (uint32_t)(nb2 * 16 * 272) + k * 32;
            ldmx4(bh[nb2], wh_sb + off);
            ldmx4(bl[nb2], wl_sb + off);
        }
#pragma unroll
        for (int nb = 0; nb < 8; nb++) {
            uint32_t b0h = bh[nb >> 1][(nb & 1) * 2], b1h = bh[nb >> 1][(nb & 1) * 2 + 1];
            uint32_t b0l = bl[nb >> 1][(nb & 1) * 2], b1l = bl[nb >> 1][(nb & 1) * 2 + 1];
            mma_bf16(acc[nb], ah, b0h, b1h);
            mma_bf16(acc[nb], al, b0h, b1h);
            mma_bf16(acc[nb], ah, b0l, b1l);
        }
    }

    // --- epilogue -------------------------------------------------------------
    int r0 = rowBase + rblk * 16 + g;
    if (out_sel == 0) {
        __half2* oh = (__half2*)g_hwh;
#pragma unroll
        for (int nb = 0; nb < 8; nb++) {
            int c = cblk * 64 + nb * 8 + 2 * tg;
            if (r0 < M)
                oh[(r0 * 128 + c) >> 1] = __floats2half2_rn(acc[nb][0], acc[nb][1]);
            if (r0 + 8 < M)
                oh[((r0 + 8) * 128 + c) >> 1] = __floats2half2_rn(acc[nb][2], acc[nb][3]);
        }
    } else {
        float* out = (out_sel == 1) ? g_A : g_B;
#pragma unroll
        for (int nb = 0; nb < 8; nb++) {
            int c = cblk * 64 + nb * 8 + 2 * tg;
            float bv0 = 0.f, bv1 = 0.f;
            if (bias) { bv0 = bias[c]; bv1 = bias[c + 1]; }
            if (r0 < M)
                *(float2*)&out[r0 * 128 + c] = make_float2(acc[nb][0] + bv0, acc[nb][1] + bv1);
            if (r0 + 8 < M)
                *(float2*)&out[(r0 + 8) * 128 + c] = make_float2(acc[nb][2] + bv0, acc[nb][3] + bv1);
        }
    }
}

// ---------------- aggregation: h[n] = relu(self + sum + bias (+res)) --------
// 2 nodes per warp, 16 lanes per node, uint4 (8 fp16 ch) per lane.
__global__ void k_agg(const float* __restrict__ bias, int residual) {
    int gw = (blockIdx.x * blockDim.x + threadIdx.x) >> 5;
    int lane = threadIdx.x & 31;
    int half = lane >> 4, hl = lane & 15;
    int n = gw * 2 + half;
    if (n >= N_NODES) return;

    const uint4* hw4 = (const uint4*)g_hwh;
    float d = g_dis[n];
    float ds = d * d;
    float4 acc0 = make_float4(0.f, 0.f, 0.f, 0.f);
    float4 acc1 = make_float4(0.f, 0.f, 0.f, 0.f);
    acc_h8(acc0, acc1, hw4[n * 16 + hl], ds);

    int e = g_indptr[n];
    int end = g_indptr[n + 1];
    for (; e + 8 <= end; e += 8) {
        int s[8]; float nr[8]; uint4 v[8];
#pragma unroll
        for (int j = 0; j < 8; j++) { s[j] = g_csr_src[e + j]; nr[j] = g_csr_nrm[e + j]; }
#pragma unroll
        for (int j = 0; j < 8; j++) v[j] = hw4[s[j] * 16 + hl];
#pragma unroll
        for (int j = 0; j < 8; j++) acc_h8(acc0, acc1, v[j], nr[j]);
    }
    if (e + 4 <= end) {
        int s[4]; float nr[4]; uint4 v[4];
#pragma unroll
        for (int j = 0; j < 4; j++) { s[j] = g_csr_src[e + j]; nr[j] = g_csr_nrm[e + j]; }
#pragma unroll
        for (int j = 0; j < 4; j++) v[j] = hw4[s[j] * 16 + hl];
#pragma unroll
        for (int j = 0; j < 4; j++) acc_h8(acc0, acc1, v[j], nr[j]);
        e += 4;
    }
    for (; e < end; e++)
        acc_h8(acc0, acc1, hw4[g_csr_src[e] * 16 + hl], g_csr_nrm[e]);

    float4 b0 = ((const float4*)bias)[hl * 2];
    float4 b1 = ((const float4*)bias)[hl * 2 + 1];
    acc0 = f4add(acc0, b0);
    acc1 = f4add(acc1, b1);
    if (residual) {
        acc0 = f4add(acc0, ((const float4*)g_h)[n * 32 + hl * 2]);
        acc1 = f4add(acc1, ((const float4*)g_h)[n * 32 + hl * 2 + 1]);
    }
    ((float4*)g_h)[n * 32 + hl * 2] = f4relu(acc0);
    ((float4*)g_h)[n * 32 + hl * 2 + 1] = f4relu(acc1);
}

// ---------------- persistent fused edge MLP (mma.sync fp16, k16) ------------
// Processes edges in CSR (dst-sorted) order: B[dst] rows are L1-deduped
// (~4-8 distinct dsts per 128-edge tile), A[src] random. Result scattered
// to out[g_csr_eid[p]]. Per-edge arithmetic identical to edge-order version.
#define ESM_US 0
#define ESM_WS 34816
#define ESM_B1 69632
#define ESM_W2 70144
#define ESM_PB 70656
#define ESM_BYTES 71680
#define N_TILES (N_EDGES / 128)
#define EDGE_GRID 296

__global__ void __launch_bounds__(256, 2) k_edge_mlp_fp16(
    const float* __restrict__ W1, const float* __restrict__ b1,
    const float* __restrict__ w2, const float* __restrict__ b2,
    float* __restrict__ out) {
    extern __shared__ char smc[];
    __half* Ws  = (__half*)(smc + ESM_WS);
    float* b1s  = (float*)(smc + ESM_B1);
    float* w2s  = (float*)(smc + ESM_W2);
    float* pbuf = (float*)(smc + ESM_PB);

    int tid = threadIdx.x;
    int lane = tid & 31, wid = tid >> 5;

#pragma unroll 4
    for (int it = 0; it < 64; it++) {
        int i = it * 256 + tid;
        int kk = i >> 7, n = i & 127;
        Ws[n * 136 + kk] = __float2half_rn(W1[i]);
    }
    if (tid < 128) { b1s[tid] = b1[tid]; w2s[tid] = w2[tid]; }
    float b2v = b2[0];
    __syncthreads();

    int rblk = wid >> 1, cblk = wid & 1;
    int g = lane >> 2, tg = lane & 3;

    uint32_t us_sb = (uint32_t)__cvta_generic_to_shared(smc + ESM_US);
    uint32_t ws_sb = (uint32_t)__cvta_generic_to_shared(smc + ESM_WS);
    uint32_t a_base = us_sb +
        (uint32_t)((rblk * 32 + (lane & 7) + (lane & 8)) * 272 + ((lane & 16) ? 16 : 0));
    uint32_t b_base = ws_sb +
        (uint32_t)((cblk * 64 + (lane & 7) + ((lane & 16) >> 1)) * 272 + (lane & 8) * 2);

    const float4* A4 = (const float4*)g_A;
    const float4* B4 = (const float4*)g_B;

    for (int tile = blockIdx.x; tile < N_TILES; tile += EDGE_GRID) {
        int p0 = tile * 128;

        // --- gather u = relu(A[src]+B[dst]) in CSR order; 2 thr/edge --------
        {
            int i = tid >> 1, h = tid & 1;
            int p = p0 + i;
            int r = g_csr_src[p] * 32, c = g_csr_dst[p] * 32;
            __half2* dst = (__half2*)(smc + ESM_US + i * 272 + h * 128);
#pragma unroll
            for (int q = 0; q < 16; q++) {
                float4 a = A4[r + h * 16 + q];
                float4 b = B4[c + h * 16 + q];
                dst[q * 2 + 0] = __floats2half2_rn(fmaxf(a.x + b.x, 0.f),
                                                   fmaxf(a.y + b.y, 0.f));
                dst[q * 2 + 1] = __floats2half2_rn(fmaxf(a.z + b.z, 0.f),
                                                   fmaxf(a.w + b.w, 0.f));
            }
        }
        __syncthreads();

        float acc[2][8][4];
#pragma unroll
        for (int mt = 0; mt < 2; mt++)
#pragma unroll
            for (int n = 0; n < 8; n++)
#pragma unroll
                for (int j = 0; j < 4; j++) acc[mt][n][j] = 0.f;

#pragma unroll
        for (int k = 0; k < 8; k++) {
            uint32_t a0[4], a1[4];
            ldmx4(a0, a_base + k * 32);
            ldmx4(a1, a_base + 16 * 272 + k * 32);
            uint32_t bf[4][4];
#pragma unroll
            for (int nb2 = 0; nb2 < 4; nb2++)
                ldmx4(bf[nb2], b_base + (uint32_t)(nb2 * 16 * 272) + k * 32);
#pragma unroll
            for (int nb = 0; nb < 8; nb++) {
                uint32_t bb0 = bf[nb >> 1][(nb & 1) * 2];
                uint32_t bb1 = bf[nb >> 1][(nb & 1) * 2 + 1];
                mma_fp16(acc[0][nb], a0, bb0, bb1);
                mma_fp16(acc[1][nb], a1, bb0, bb1);
            }
        }

#pragma unroll
        for (int mt = 0; mt < 2; mt++) {
            float p0v = 0.f, p1v = 0.f;
#pragma unroll
            for (int nb = 0; nb < 8; nb++) {
                int c0 = cblk * 64 + nb * 8 + 2 * tg;
                float wv0 = w2s[c0], wv1 = w2s[c0 + 1];
                float bb0 = b1s[c0], bb1 = b1s[c0 + 1];
                p0v += fmaxf(acc[mt][nb][0] + bb0, 0.f) * wv0 + fmaxf(acc[mt][nb][1] + bb1, 0.f) * wv1;
                p1v += fmaxf(acc[mt][nb][2] + bb0, 0.f) * wv0 + fmaxf(acc[mt][nb][3] + bb1, 0.f) * wv1;
            }
            p0v += __shfl_xor_sync(0xffffffffu, p0v, 1);
            p0v += __shfl_xor_sync(0xffffffffu, p0v, 2);
            p1v += __shfl_xor_sync(0xffffffffu, p1v, 1);
            p1v += __shfl_xor_sync(0xffffffffu, p1v, 2);
            if (tg == 0) {
                int rr = rblk * 32 + mt * 16 + g;
                pbuf[cblk * 128 + rr] = p0v;
                pbuf[cblk * 128 + rr + 8] = p1v;
            }
        }
        __syncthreads();
        if (tid < 128)
            out[g_csr_eid[p0 + tid]] = pbuf[tid] + pbuf[128 + tid] + b2v;
        __syncthreads();
    }
}

// ---------------- launch -----------------------------------------------------
extern "C" void kernel_launch(void* const* d_in, const int* in_sizes, int n_in,
                              void* d_out, int out_size) {
    const float* x       = (const float*)d_in[0];
    const int*   ei      = (const int*)d_in[1];
    const float* convs_W = (const float*)d_in[2];
    const float* convs_b = (const float*)d_in[3];
    const float* fc0_W   = (const float*)d_in[4];
    const float* fc0_b   = (const float*)d_in[5];
    const float* fc1_W   = (const float*)d_in[6];
    const float* fc1_b   = (const float*)d_in[7];
    const float* fc2_W   = (const float*)d_in[8];
    const float* fc2_b   = (const float*)d_in[9];
    float* out = (float*)d_out;

    const int* row = ei;
    const int* col = ei + N_EDGES;

    cudaFuncSetAttribute(k_sgemm_tc, cudaFuncAttributeMaxDynamicSharedMemorySize, SGT_BYTES);
    cudaFuncSetAttribute(k_edge_mlp_fp16, cudaFuncAttributeMaxDynamicSharedMemorySize, ESM_BYTES);

    const int GRID_GEMM = (N_NODES + 63) / 64;
    const int GRID_AGG  = (N_NODES * 16 + 255) / 256;

    // 1. setup (sgemm L0 in the profiled 4th slot)
    k_split_w<<<(10 * 16384 + 255) / 256, 256>>>(convs_W, fc0_W);
    k_zero_deg<<<(N_NODES + 255) / 256, 256>>>();
    k_count_deg<<<(N_EDGES + 255) / 256, 256>>>(col);
    k_sgemm_tc<<<GRID_GEMM, 256, SGT_BYTES>>>(x, 0, 0, 0, nullptr, N_NODES);   // L0 GEMM
    k_scan_dis<<<1, 1024>>>();
    k_fill_csr<<<(N_EDGES + 255) / 256, 256>>>(row, col);
    k_agg<<<GRID_AGG, 256>>>(convs_b, 0);                                      // L0 agg

    // 2. GCN layers 1..7
    for (int l = 1; l < N_LAYERS; l++) {
        k_sgemm_tc<<<GRID_GEMM, 256, SGT_BYTES>>>(x, 1, 0, l, nullptr, N_NODES);
        k_agg<<<GRID_AGG, 256>>>(convs_b + l * CDIM, 1);
    }

    // 3. factorized fc0: A = h@W0a + b0, B = h@W0b
    k_sgemm_tc<<<GRID_GEMM, 256, SGT_BYTES>>>(nullptr, 1, 1, 8, fc0_b, N_NODES);
    k_sgemm_tc<<<GRID_GEMM, 256, SGT_BYTES>>>(nullptr, 1, 2, 9, nullptr, N_NODES);

    // 4. persistent fused edge MLP, CSR order (B rows L1-deduped)
    k_edge_mlp_fp16<<<EDGE_GRID, 256, ESM_BYTES>>>(fc1_W, fc1_b, fc2_W, fc2_b, out);
}

// round 14
// speedup vs baseline: 1.4094x; 1.0181x over previous
#include <cuda_runtime.h>
#include <cuda_bf16.h>
#include <cuda_fp16.h>
#include <cstdint>

#define N_NODES 50000
#define N_EDGES 1600000
#define CDIM 128
#define N_LAYERS 8

// ---------------- scratch (device globals; no allocation allowed) ----------
__device__ float  g_h [N_NODES * CDIM];    // fp32 node features (residual / fc0 input)
__device__ __half g_hwh[N_NODES * CDIM];   // fp16 transformed features (gather table)
__device__ float  g_A [N_NODES * CDIM];
__device__ float  g_B [N_NODES * CDIM];
__device__ float  g_dis[N_NODES];
__device__ int    g_deg[N_NODES];
__device__ int    g_indptr[N_NODES + 1];
__device__ int    g_cursor[N_NODES];
__device__ int    g_csr_src[N_EDGES];
__device__ int    g_csr_dst[N_EDGES];
__device__ int    g_csr_eid[N_EDGES];
__device__ float  g_csr_nrm[N_EDGES];
// transposed + bf16 hi/lo-split weights for node GEMMs: [10][n=128][k=128]
__device__ __nv_bfloat16 g_Wth[10 * 128 * 128];
__device__ __nv_bfloat16 g_Wtl[10 * 128 * 128];

// ---------------- helpers ----------------------------------------------------
__device__ __forceinline__ void mma_bf16(float d[4], const uint32_t a[4],
                                         uint32_t b0, uint32_t b1) {
    asm volatile(
        "mma.sync.aligned.m16n8k16.row.col.f32.bf16.bf16.f32 "
        "{%0,%1,%2,%3}, {%4,%5,%6,%7}, {%8,%9}, {%0,%1,%2,%3};"
        : "+f"(d[0]), "+f"(d[1]), "+f"(d[2]), "+f"(d[3])
        : "r"(a[0]), "r"(a[1]), "r"(a[2]), "r"(a[3]), "r"(b0), "r"(b1));
}
__device__ __forceinline__ void mma_fp16(float d[4], const uint32_t a[4],
                                         uint32_t b0, uint32_t b1) {
    asm volatile(
        "mma.sync.aligned.m16n8k16.row.col.f32.f16.f16.f32 "
        "{%0,%1,%2,%3}, {%4,%5,%6,%7}, {%8,%9}, {%0,%1,%2,%3};"
        : "+f"(d[0]), "+f"(d[1]), "+f"(d[2]), "+f"(d[3])
        : "r"(a[0]), "r"(a[1]), "r"(a[2]), "r"(a[3]), "r"(b0), "r"(b1));
}
__device__ __forceinline__ void ldmx4(uint32_t r[4], uint32_t addr) {
    asm volatile("ldmatrix.sync.aligned.m8n8.x4.shared.b16 {%0,%1,%2,%3}, [%4];"
                 : "=r"(r[0]), "=r"(r[1]), "=r"(r[2]), "=r"(r[3]) : "r"(addr));
}
__device__ __forceinline__ float4 f4add(float4 a, float4 b) {
    return make_float4(a.x + b.x, a.y + b.y, a.z + b.z, a.w + b.w);
}
__device__ __forceinline__ float4 f4relu(float4 a) {
    return make_float4(fmaxf(a.x, 0.f), fmaxf(a.y, 0.f), fmaxf(a.z, 0.f), fmaxf(a.w, 0.f));
}
__device__ __forceinline__ uint32_t pack_bf16(float a, float b) {
    uint32_t lo = (uint32_t)__bfloat16_as_ushort(__float2bfloat16(a));
    uint32_t hi = (uint32_t)__bfloat16_as_ushort(__float2bfloat16(b));
    return lo | (hi << 16);
}
// accumulate 8 fp16 channels (uint4) scaled by nr into two float4s
__device__ __forceinline__ void acc_h8(float4& a0, float4& a1, uint4 raw, float nr) {
    __half2 h0 = *(__half2*)&raw.x;
    __half2 h1 = *(__half2*)&raw.y;
    __half2 h2 = *(__half2*)&raw.z;
    __half2 h3 = *(__half2*)&raw.w;
    float2 f0 = __half22float2(h0);
    float2 f1 = __half22float2(h1);
    float2 f2 = __half22float2(h2);
    float2 f3 = __half22float2(h3);
    a0.x += nr * f0.x; a0.y += nr * f0.y;
    a0.z += nr * f1.x; a0.w += nr * f1.y;
    a1.x += nr * f2.x; a1.y += nr * f2.y;
    a1.z += nr * f3.x; a1.w += nr * f3.y;
}

// ---------------- setup kernels ---------------------------------------------
__global__ void k_zero_deg() {
    int i = blockIdx.x * blockDim.x + threadIdx.x;
    if (i < N_NODES) g_deg[i] = 0;
}

__global__ void k_count_deg(const int* __restrict__ col) {
    int e = blockIdx.x * blockDim.x + threadIdx.x;
    if (e < N_EDGES) atomicAdd(&g_deg[col[e]], 1);
}

// warp-shuffle based scan: 3 syncs per 1024-chunk instead of 20
__global__ void k_scan_dis() {
    __shared__ int wsum[32];
    __shared__ int s_carry;
    int t = threadIdx.x, lane = t & 31, wd = t >> 5;
    if (t == 0) s_carry = 0;
    __syncthreads();
    for (int base = 0; base < N_NODES; base += 1024) {
        int idx = base + t;
        int v = (idx < N_NODES) ? g_deg[idx] : 0;
        int x = v;
#pragma unroll
        for (int off = 1; off < 32; off <<= 1) {
            int y = __shfl_up_sync(0xffffffffu, x, off);
            if (lane >= off) x += y;
        }
        if (lane == 31) wsum[wd] = x;
        __syncthreads();
        if (wd == 0) {
            int w = wsum[lane];
#pragma unroll
            for (int off = 1; off < 32; off <<= 1) {
                int y = __shfl_up_sync(0xffffffffu, w, off);
                if (lane >= off) w += y;
            }
            wsum[lane] = w;   // inclusive prefix over warp sums
        }
        __syncthreads();
        int warp_prefix = (wd == 0) ? 0 : wsum[wd - 1];
        int incl = warp_prefix + x;
        int carry = s_carry;
        if (idx < N_NODES) {
            int excl = carry + incl - v;
            g_indptr[idx] = excl;
            g_cursor[idx] = excl;
            g_dis[idx] = rsqrtf((float)(v + 1));
        }
        __syncthreads();
        if (t == 1023) s_carry = carry + incl;
        __syncthreads();
    }
    if (t == 0) g_indptr[N_NODES] = s_carry;
}

__global__ void k_fill_csr(const int* __restrict__ row, const int* __restrict__ col) {
    int e = blockIdx.x * blockDim.x + threadIdx.x;
    if (e < N_EDGES) {
        int r = row[e], c = col[e];
        float nrm = g_dis[r] * g_dis[c];
        int pos = atomicAdd(&g_cursor[c], 1);
        g_csr_src[pos] = r;
        g_csr_dst[pos] = c;
        g_csr_eid[pos] = e;
        g_csr_nrm[pos] = nrm;
    }
}

// ---------------- W transpose + bf16 hi/lo split (once) ---------------------
__global__ void k_split_w(const float* __restrict__ convs_W,
                          const float* __restrict__ fc0_W) {
    int idx = blockIdx.x * 256 + threadIdx.x;
    if (idx >= 10 * 16384) return;
    int l = idx >> 14;
    int kk = (idx >> 7) & 127;
    int n = idx & 127;
    float v = (l < 8) ? convs_W[idx] : fc0_W[idx - 8 * 16384];
    __nv_bfloat16 hi = __float2bfloat16(v);
    float lo = v - __bfloat162float(hi);
    int dst = (l << 14) + (n << 7) + kk;
    g_Wth[dst] = hi;
    g_Wtl[dst] = __float2bfloat16(lo);
}

// ---------------- tensor-core node GEMM (bf16x2 3-pass, ~fp32 accurate) -----
// CTA tile: 64 rows x 64 cols (n-half picked by blockIdx.y). 256 thr/8 warps,
// warp tile m16 x n32. Smem 69.6 KB -> 3 CTAs/SM. Same 3-pass math as before
// (bit-identical results; only the CTA/N decomposition changed).
#define SGT_XH 0
#define SGT_XL 17408
#define SGT_WH 34816
#define SGT_WL 52224
#define SGT_BYTES 69632

__global__ void __launch_bounds__(256, 3) k_sgemm_tc(
    const float* __restrict__ Aext, int a_sel, int out_sel, int layer,
    const float* __restrict__ bias, int M) {
    extern __shared__ char smc[];
    const float* Ain = a_sel ? g_h : Aext;

    int tid = threadIdx.x;
    int lane = tid & 31, wid = tid >> 5;
    int rowBase = blockIdx.x * 64;
    int nBase = blockIdx.y * 64;

    // --- stage X split (64 x 128 fp32 -> hi/lo bf16, stride 136) ------------
    {
        const float4* A4 = (const float4*)Ain;
        uint32_t* Xh32 = (uint32_t*)(smc + SGT_XH);
        uint32_t* Xl32 = (uint32_t*)(smc + SGT_XL);
#pragma unroll
        for (int i = 0; i < 8; i++) {
            int idx = tid + i * 256;
            int rr = idx >> 5, c4 = idx & 31;
            float4 v = make_float4(0.f, 0.f, 0.f, 0.f);
            if (rowBase + rr < M) v = A4[(rowBase + rr) * 32 + c4];
            __nv_bfloat16 h0 = __float2bfloat16(v.x);
            __nv_bfloat16 h1 = __float2bfloat16(v.y);
            __nv_bfloat16 h2 = __float2bfloat16(v.z);
            __nv_bfloat16 h3 = __float2bfloat16(v.w);
            uint32_t hp0 = (uint32_t)__bfloat16_as_ushort(h0) |
                           ((uint32_t)__bfloat16_as_ushort(h1) << 16);
            uint32_t hp1 = (uint32_t)__bfloat16_as_ushort(h2) |
                           ((uint32_t)__bfloat16_as_ushort(h3) << 16);
            uint32_t lp0 = pack_bf16(v.x - __bfloat162float(h0), v.y - __bfloat162float(h1));
            uint32_t lp1 = pack_bf16(v.z - __bfloat162float(h2), v.w - __bfloat162float(h3));
            int o = rr * 68 + c4 * 2;
            *(uint2*)&Xh32[o] = make_uint2(hp0, hp1);
            *(uint2*)&Xl32[o] = make_uint2(lp0, lp1);
        }
    }
    // --- stage W hi/lo: 64 n-rows of this half (pre-transposed [n][k]) ------
    {
        const uint4* Wh4 = (const uint4*)(g_Wth + layer * 16384 + nBase * 128);
        const uint4* Wl4 = (const uint4*)(g_Wtl + layer * 16384 + nBase * 128);
#pragma unroll
        for (int i = 0; i < 4; i++) {
            int idx = tid + i * 256;       // 1024 uint4
            int rr = idx >> 4, c8 = idx & 15;
            *(uint4*)(smc + SGT_WH + rr * 272 + c8 * 16) = Wh4[rr * 16 + c8];
            *(uint4*)(smc + SGT_WL + rr * 272 + c8 * 16) = Wl4[rr * 16 + c8];
        }
    }
    __syncthreads();

    int g = lane >> 2, tg = lane & 3;
    int rblk = wid >> 1, cblk = wid & 1;   // m: 4 x 16 rows, n: 2 x 32 cols

    float acc[4][4];
#pragma unroll
    for (int n = 0; n < 4; n++)
#pragma unroll
        for (int j = 0; j < 4; j++) acc[n][j] = 0.f;

    uint32_t xh_sb = (uint32_t)__cvta_generic_to_shared(smc + SGT_XH);
    uint32_t xl_sb = (uint32_t)__cvta_generic_to_shared(smc + SGT_XL);
    uint32_t wh_sb = (uint32_t)__cvta_generic_to_shared(smc + SGT_WH);
    uint32_t wl_sb = (uint32_t)__cvta_generic_to_shared(smc + SGT_WL);

    int a_r = rblk * 16 + (lane & 7) + (lane & 8);
    int a_kel = (lane & 16) ? 8 : 0;
    uint32_t a_hi_base = xh_sb + (uint32_t)(a_r * 272 + a_kel * 2);
    uint32_t a_lo_base = xl_sb + (uint32_t)(a_r * 272 + a_kel * 2);
    int b_nloc = (lane & 7) + ((lane & 16) >> 1);
    int b_kel = (lane & 8);
    uint32_t b_rowoff = (uint32_t)((cblk * 32 + b_nloc) * 272 + b_kel * 2);

#pragma unroll
    for (int k = 0; k < 8; k++) {
        uint32_t ah[4], al[4];
        ldmx4(ah, a_hi_base + k * 32);
        ldmx4(al, a_lo_base + k * 32);
        uint32_t bh[2][4], bl[2][4];
#pragma unroll
        for (int nb2 = 0; nb2 < 2; nb2++) {
            uint32_t off = b_rowoff + (uint32_t)(nb2 * 16 * 272) + k * 32;
            ldmx4(bh[nb2], wh_sb + off);
            ldmx4(bl[nb2], wl_sb + off);
        }
#pragma unroll
        for (int nb = 0; nb < 4; nb++) {
            uint32_t b0h = bh[nb >> 1][(nb & 1) * 2], b1h = bh[nb >> 1][(nb & 1) * 2 + 1];
            uint32_t b0l = bl[nb >> 1][(nb & 1) * 2], b1l = bl[nb >> 1][(nb & 1) * 2 + 1];
            mma_bf16(acc[nb], ah, b0h, b1h);
            mma_bf16(acc[nb], al, b0h, b1h);
            mma_bf16(acc[nb], ah, b0l, b1l);
        }
    }

    // --- epilogue -------------------------------------------------------------
    int r0 = rowBase + rblk * 16 + g;
    if (out_sel == 0) {
        __half2* oh = (__half2*)g_hwh;
#pragma unroll
        for (int nb = 0; nb < 4; nb++) {
            int c = nBase + cblk * 32 + nb * 8 + 2 * tg;
            if (r0 < M)
                oh[(r0 * 128 + c) >> 1] = __floats2half2_rn(acc[nb][0], acc[nb][1]);
            if (r0 + 8 < M)
                oh[((r0 + 8) * 128 + c) >> 1] = __floats2half2_rn(acc[nb][2], acc[nb][3]);
        }
    } else {
        float* out = (out_sel == 1) ? g_A : g_B;
#pragma unroll
        for (int nb = 0; nb < 4; nb++) {
            int c = nBase + cblk * 32 + nb * 8 + 2 * tg;
            float bv0 = 0.f, bv1 = 0.f;
            if (bias) { bv0 = bias[c]; bv1 = bias[c + 1]; }
            if (r0 < M)
                *(float2*)&out[r0 * 128 + c] = make_float2(acc[nb][0] + bv0, acc[nb][1] + bv1);
            if (r0 + 8 < M)
                *(float2*)&out[(r0 + 8) * 128 + c] = make_float2(acc[nb][2] + bv0, acc[nb][3] + bv1);
        }
    }
}

// ---------------- aggregation: h[n] = relu(self + sum + bias (+res)) --------
// 2 nodes per warp, 16 lanes per node, uint4 (8 fp16 ch) per lane.
__global__ void k_agg(const float* __restrict__ bias, int residual) {
    int gw = (blockIdx.x * blockDim.x + threadIdx.x) >> 5;
    int lane = threadIdx.x & 31;
    int half = lane >> 4, hl = lane & 15;
    int n = gw * 2 + half;
    if (n >= N_NODES) return;

    const uint4* hw4 = (const uint4*)g_hwh;
    float d = g_dis[n];
    float ds = d * d;
    float4 acc0 = make_float4(0.f, 0.f, 0.f, 0.f);
    float4 acc1 = make_float4(0.f, 0.f, 0.f, 0.f);
    acc_h8(acc0, acc1, hw4[n * 16 + hl], ds);

    int e = g_indptr[n];
    int end = g_indptr[n + 1];
    for (; e + 8 <= end; e += 8) {
        int s[8]; float nr[8]; uint4 v[8];
#pragma unroll
        for (int j = 0; j < 8; j++) { s[j] = g_csr_src[e + j]; nr[j] = g_csr_nrm[e + j]; }
#pragma unroll
        for (int j = 0; j < 8; j++) v[j] = hw4[s[j] * 16 + hl];
#pragma unroll
        for (int j = 0; j < 8; j++) acc_h8(acc0, acc1, v[j], nr[j]);
    }
    if (e + 4 <= end) {
        int s[4]; float nr[4]; uint4 v[4];
#pragma unroll
        for (int j = 0; j < 4; j++) { s[j] = g_csr_src[e + j]; nr[j] = g_csr_nrm[e + j]; }
#pragma unroll
        for (int j = 0; j < 4; j++) v[j] = hw4[s[j] * 16 + hl];
#pragma unroll
        for (int j = 0; j < 4; j++) acc_h8(acc0, acc1, v[j], nr[j]);
        e += 4;
    }
    for (; e < end; e++)
        acc_h8(acc0, acc1, hw4[g_csr_src[e] * 16 + hl], g_csr_nrm[e]);

    float4 b0 = ((const float4*)bias)[hl * 2];
    float4 b1 = ((const float4*)bias)[hl * 2 + 1];
    acc0 = f4add(acc0, b0);
    acc1 = f4add(acc1, b1);
    if (residual) {
        acc0 = f4add(acc0, ((const float4*)g_h)[n * 32 + hl * 2]);
        acc1 = f4add(acc1, ((const float4*)g_h)[n * 32 + hl * 2 + 1]);
    }
    ((float4*)g_h)[n * 32 + hl * 2] = f4relu(acc0);
    ((float4*)g_h)[n * 32 + hl * 2 + 1] = f4relu(acc1);
}

// ---------------- persistent fused edge MLP (mma.sync fp16, k16) ------------
// CSR (dst-sorted) order: B[dst] rows L1-deduped, scatter to out[eid].
#define ESM_US 0
#define ESM_WS 34816
#define ESM_B1 69632
#define ESM_W2 70144
#define ESM_PB 70656
#define ESM_BYTES 71680
#define N_TILES (N_EDGES / 128)
#define EDGE_GRID 296

__global__ void __launch_bounds__(256, 2) k_edge_mlp_fp16(
    const float* __restrict__ W1, const float* __restrict__ b1,
    const float* __restrict__ w2, const float* __restrict__ b2,
    float* __restrict__ out) {
    extern __shared__ char smc[];
    __half* Ws  = (__half*)(smc + ESM_WS);
    float* b1s  = (float*)(smc + ESM_B1);
    float* w2s  = (float*)(smc + ESM_W2);
    float* pbuf = (float*)(smc + ESM_PB);

    int tid = threadIdx.x;
    int lane = tid & 31, wid = tid >> 5;

#pragma unroll 4
    for (int it = 0; it < 64; it++) {
        int i = it * 256 + tid;
        int kk = i >> 7, n = i & 127;
        Ws[n * 136 + kk] = __float2half_rn(W1[i]);
    }
    if (tid < 128) { b1s[tid] = b1[tid]; w2s[tid] = w2[tid]; }
    float b2v = b2[0];
    __syncthreads();

    int rblk = wid >> 1, cblk = wid & 1;
    int g = lane >> 2, tg = lane & 3;

    uint32_t us_sb = (uint32_t)__cvta_generic_to_shared(smc + ESM_US);
    uint32_t ws_sb = (uint32_t)__cvta_generic_to_shared(smc + ESM_WS);
    uint32_t a_base = us_sb +
        (uint32_t)((rblk * 32 + (lane & 7) + (lane & 8)) * 272 + ((lane & 16) ? 16 : 0));
    uint32_t b_base = ws_sb +
        (uint32_t)((cblk * 64 + (lane & 7) + ((lane & 16) >> 1)) * 272 + (lane & 8) * 2);

    const float4* A4 = (const float4*)g_A;
    const float4* B4 = (const float4*)g_B;

    for (int tile = blockIdx.x; tile < N_TILES; tile += EDGE_GRID) {
        int p0 = tile * 128;

        // --- gather u = relu(A[src]+B[dst]) in CSR order; 2 thr/edge --------
        {
            int i = tid >> 1, h = tid & 1;
            int p = p0 + i;
            int r = g_csr_src[p] * 32, c = g_csr_dst[p] * 32;
            __half2* dst = (__half2*)(smc + ESM_US + i * 272 + h * 128);
#pragma unroll
            for (int q = 0; q < 16; q++) {
                float4 a = A4[r + h * 16 + q];
                float4 b = B4[c + h * 16 + q];
                dst[q * 2 + 0] = __floats2half2_rn(fmaxf(a.x + b.x, 0.f),
                                                   fmaxf(a.y + b.y, 0.f));
                dst[q * 2 + 1] = __floats2half2_rn(fmaxf(a.z + b.z, 0.f),
                                                   fmaxf(a.w + b.w, 0.f));
            }
        }
        __syncthreads();

        float acc[2][8][4];
#pragma unroll
        for (int mt = 0; mt < 2; mt++)
#pragma unroll
            for (int n = 0; n < 8; n++)
#pragma unroll
                for (int j = 0; j < 4; j++) acc[mt][n][j] = 0.f;

#pragma unroll
        for (int k = 0; k < 8; k++) {
            uint32_t a0[4], a1[4];
            ldmx4(a0, a_base + k * 32);
            ldmx4(a1, a_base + 16 * 272 + k * 32);
            uint32_t bf[4][4];
#pragma unroll
            for (int nb2 = 0; nb2 < 4; nb2++)
                ldmx4(bf[nb2], b_base + (uint32_t)(nb2 * 16 * 272) + k * 32);
#pragma unroll
            for (int nb = 0; nb < 8; nb++) {
                uint32_t bb0 = bf[nb >> 1][(nb & 1) * 2];
                uint32_t bb1 = bf[nb >> 1][(nb & 1) * 2 + 1];
                mma_fp16(acc[0][nb], a0, bb0, bb1);
                mma_fp16(acc[1][nb], a1, bb0, bb1);
            }
        }

#pragma unroll
        for (int mt = 0; mt < 2; mt++) {
            float p0v = 0.f, p1v = 0.f;
#pragma unroll
            for (int nb = 0; nb < 8; nb++) {
                int c0 = cblk * 64 + nb * 8 + 2 * tg;
                float wv0 = w2s[c0], wv1 = w2s[c0 + 1];
                float bb0 = b1s[c0], bb1 = b1s[c0 + 1];
                p0v += fmaxf(acc[mt][nb][0] + bb0, 0.f) * wv0 + fmaxf(acc[mt][nb][1] + bb1, 0.f) * wv1;
                p1v += fmaxf(acc[mt][nb][2] + bb0, 0.f) * wv0 + fmaxf(acc[mt][nb][3] + bb1, 0.f) * wv1;
            }
            p0v += __shfl_xor_sync(0xffffffffu, p0v, 1);
            p0v += __shfl_xor_sync(0xffffffffu, p0v, 2);
            p1v += __shfl_xor_sync(0xffffffffu, p1v, 1);
            p1v += __shfl_xor_sync(0xffffffffu, p1v, 2);
            if (tg == 0) {
                int rr = rblk * 32 + mt * 16 + g;
                pbuf[cblk * 128 + rr] = p0v;
                pbuf[cblk * 128 + rr + 8] = p1v;
            }
        }
        __syncthreads();
        if (tid < 128)
            out[g_csr_eid[p0 + tid]] = pbuf[tid] + pbuf[128 + tid] + b2v;
        __syncthreads();
    }
}

// ---------------- launch -----------------------------------------------------
extern "C" void kernel_launch(void* const* d_in, const int* in_sizes, int n_in,
                              void* d_out, int out_size) {
    const float* x       = (const float*)d_in[0];
    const int*   ei      = (const int*)d_in[1];
    const float* convs_W = (const float*)d_in[2];
    const float* convs_b = (const float*)d_in[3];
    const float* fc0_W   = (const float*)d_in[4];
    const float* fc0_b   = (const float*)d_in[5];
    const float* fc1_W   = (const float*)d_in[6];
    const float* fc1_b   = (const float*)d_in[7];
    const float* fc2_W   = (const float*)d_in[8];
    const float* fc2_b   = (const float*)d_in[9];
    float* out = (float*)d_out;

    const int* row = ei;
    const int* col = ei + N_EDGES;

    cudaFuncSetAttribute(k_sgemm_tc, cudaFuncAttributeMaxDynamicSharedMemorySize, SGT_BYTES);
    cudaFuncSetAttribute(k_edge_mlp_fp16, cudaFuncAttributeMaxDynamicSharedMemorySize, ESM_BYTES);

    const dim3 GRID_GEMM((N_NODES + 63) / 64, 2);
    const int GRID_AGG = (N_NODES * 16 + 255) / 256;

    // 1. setup (sgemm L0 in the profiled 4th slot)
    k_split_w<<<(10 * 16384 + 255) / 256, 256>>>(convs_W, fc0_W);
    k_zero_deg<<<(N_NODES + 255) / 256, 256>>>();
    k_count_deg<<<(N_EDGES + 255) / 256, 256>>>(col);
    k_sgemm_tc<<<GRID_GEMM, 256, SGT_BYTES>>>(x, 0, 0, 0, nullptr, N_NODES);   // L0 GEMM
    k_scan_dis<<<1, 1024>>>();
    k_fill_csr<<<(N_EDGES + 255) / 256, 256>>>(row, col);
    k_agg<<<GRID_AGG, 256>>>(convs_b, 0);                                      // L0 agg

    // 2. GCN layers 1..7
    for (int l = 1; l < N_LAYERS; l++) {
        k_sgemm_tc<<<GRID_GEMM, 256, SGT_BYTES>>>(x, 1, 0, l, nullptr, N_NODES);
        k_agg<<<GRID_AGG, 256>>>(convs_b + l * CDIM, 1);
    }

    // 3. factorized fc0: A = h@W0a + b0, B = h@W0b
    k_sgemm_tc<<<GRID_GEMM, 256, SGT_BYTES>>>(nullptr, 1, 1, 8, fc0_b, N_NODES);
    k_sgemm_tc<<<GRID_GEMM, 256, SGT_BYTES>>>(nullptr, 1, 2, 9, nullptr, N_NODES);

    // 4. persistent fused edge MLP, CSR order (B rows L1-deduped)
    k_edge_mlp_fp16<<<EDGE_GRID, 256, ESM_BYTES>>>(fc1_W, fc1_b, fc2_W, fc2_b, out);
}

// round 15
// speedup vs baseline: 1.5146x; 1.0746x over previous
#include <cuda_runtime.h>
#include <cuda_bf16.h>
#include <cuda_fp16.h>
#include <cstdint>

#define N_NODES 50000
#define N_EDGES 1600000
#define CDIM 128
#define N_LAYERS 8

// ---------------- scratch (device globals; no allocation allowed) ----------
__device__ float  g_h [N_NODES * CDIM];    // fp32 node features (residual / fc0 input)
__device__ __half g_hwh[N_NODES * CDIM];   // fp16 transformed features (gather table)
__device__ float  g_A [N_NODES * CDIM];
__device__ float  g_B [N_NODES * CDIM];
__device__ float  g_dis[N_NODES];
__device__ int    g_deg[N_NODES];
__device__ int    g_indptr[N_NODES + 1];
__device__ int    g_cursor[N_NODES];
__device__ int    g_csr_src[N_EDGES];
__device__ int    g_csr_dst[N_EDGES];
__device__ int    g_csr_eid[N_EDGES];
__device__ float  g_csr_nrm[N_EDGES];
// transposed + bf16 hi/lo-split weights for node GEMMs: [10][n=128][k=128]
__device__ __nv_bfloat16 g_Wth[10 * 128 * 128];
__device__ __nv_bfloat16 g_Wtl[10 * 128 * 128];

// ---------------- helpers ----------------------------------------------------
__device__ __forceinline__ void mma_bf16(float d[4], const uint32_t a[4],
                                         uint32_t b0, uint32_t b1) {
    asm volatile(
        "mma.sync.aligned.m16n8k16.row.col.f32.bf16.bf16.f32 "
        "{%0,%1,%2,%3}, {%4,%5,%6,%7}, {%8,%9}, {%0,%1,%2,%3};"
        : "+f"(d[0]), "+f"(d[1]), "+f"(d[2]), "+f"(d[3])
        : "r"(a[0]), "r"(a[1]), "r"(a[2]), "r"(a[3]), "r"(b0), "r"(b1));
}
__device__ __forceinline__ void mma_fp16(float d[4], const uint32_t a[4],
                                         uint32_t b0, uint32_t b1) {
    asm volatile(
        "mma.sync.aligned.m16n8k16.row.col.f32.f16.f16.f32 "
        "{%0,%1,%2,%3}, {%4,%5,%6,%7}, {%8,%9}, {%0,%1,%2,%3};"
        : "+f"(d[0]), "+f"(d[1]), "+f"(d[2]), "+f"(d[3])
        : "r"(a[0]), "r"(a[1]), "r"(a[2]), "r"(a[3]), "r"(b0), "r"(b1));
}
__device__ __forceinline__ void ldmx4(uint32_t r[4], uint32_t addr) {
    asm volatile("ldmatrix.sync.aligned.m8n8.x4.shared.b16 {%0,%1,%2,%3}, [%4];"
                 : "=r"(r[0]), "=r"(r[1]), "=r"(r[2]), "=r"(r[3]) : "r"(addr));
}
__device__ __forceinline__ float4 f4add(float4 a, float4 b) {
    return make_float4(a.x + b.x, a.y + b.y, a.z + b.z, a.w + b.w);
}
__device__ __forceinline__ float4 f4relu(float4 a) {
    return make_float4(fmaxf(a.x, 0.f), fmaxf(a.y, 0.f), fmaxf(a.z, 0.f), fmaxf(a.w, 0.f));
}
__device__ __forceinline__ uint32_t pack_bf16(float a, float b) {
    uint32_t lo = (uint32_t)__bfloat16_as_ushort(__float2bfloat16(a));
    uint32_t hi = (uint32_t)__bfloat16_as_ushort(__float2bfloat16(b));
    return lo | (hi << 16);
}
// accumulate 8 fp16 channels (uint4) scaled by nr into two float4s
__device__ __forceinline__ void acc_h8(float4& a0, float4& a1, uint4 raw, float nr) {
    __half2 h0 = *(__half2*)&raw.x;
    __half2 h1 = *(__half2*)&raw.y;
    __half2 h2 = *(__half2*)&raw.z;
    __half2 h3 = *(__half2*)&raw.w;
    float2 f0 = __half22float2(h0);
    float2 f1 = __half22float2(h1);
    float2 f2 = __half22float2(h2);
    float2 f3 = __half22float2(h3);
    a0.x += nr * f0.x; a0.y += nr * f0.y;
    a0.z += nr * f1.x; a0.w += nr * f1.y;
    a1.x += nr * f2.x; a1.y += nr * f2.y;
    a1.z += nr * f3.x; a1.w += nr * f3.y;
}

// ---------------- setup kernels ---------------------------------------------
__global__ void k_zero_deg() {
    int i = blockIdx.x * blockDim.x + threadIdx.x;
    if (i < N_NODES) g_deg[i] = 0;
}

__global__ void k_count_deg(const int* __restrict__ col) {
    int e = blockIdx.x * blockDim.x + threadIdx.x;
    if (e < N_EDGES) atomicAdd(&g_deg[col[e]], 1);
}

// warp-shuffle based scan: 3 syncs per 1024-chunk
__global__ void k_scan_dis() {
    __shared__ int wsum[32];
    __shared__ int s_carry;
    int t = threadIdx.x, lane = t & 31, wd = t >> 5;
    if (t == 0) s_carry = 0;
    __syncthreads();
    for (int base = 0; base < N_NODES; base += 1024) {
        int idx = base + t;
        int v = (idx < N_NODES) ? g_deg[idx] : 0;
        int x = v;
#pragma unroll
        for (int off = 1; off < 32; off <<= 1) {
            int y = __shfl_up_sync(0xffffffffu, x, off);
            if (lane >= off) x += y;
        }
        if (lane == 31) wsum[wd] = x;
        __syncthreads();
        if (wd == 0) {
            int w = wsum[lane];
#pragma unroll
            for (int off = 1; off < 32; off <<= 1) {
                int y = __shfl_up_sync(0xffffffffu, w, off);
                if (lane >= off) w += y;
            }
            wsum[lane] = w;
        }
        __syncthreads();
        int warp_prefix = (wd == 0) ? 0 : wsum[wd - 1];
        int incl = warp_prefix + x;
        int carry = s_carry;
        if (idx < N_NODES) {
            int excl = carry + incl - v;
            g_indptr[idx] = excl;
            g_cursor[idx] = excl;
            g_dis[idx] = rsqrtf((float)(v + 1));
        }
        __syncthreads();
        if (t == 1023) s_carry = carry + incl;
        __syncthreads();
    }
    if (t == 0) g_indptr[N_NODES] = s_carry;
}

__global__ void k_fill_csr(const int* __restrict__ row, const int* __restrict__ col) {
    int e = blockIdx.x * blockDim.x + threadIdx.x;
    if (e < N_EDGES) {
        int r = row[e], c = col[e];
        float nrm = g_dis[r] * g_dis[c];
        int pos = atomicAdd(&g_cursor[c], 1);
        g_csr_src[pos] = r;
        g_csr_dst[pos] = c;
        g_csr_eid[pos] = e;
        g_csr_nrm[pos] = nrm;
    }
}

// ---------------- W transpose + bf16 hi/lo split (once) ---------------------
__global__ void k_split_w(const float* __restrict__ convs_W,
                          const float* __restrict__ fc0_W) {
    int idx = blockIdx.x * 256 + threadIdx.x;
    if (idx >= 10 * 16384) return;
    int l = idx >> 14;
    int kk = (idx >> 7) & 127;
    int n = idx & 127;
    float v = (l < 8) ? convs_W[idx] : fc0_W[idx - 8 * 16384];
    __nv_bfloat16 hi = __float2bfloat16(v);
    float lo = v - __bfloat162float(hi);
    int dst = (l << 14) + (n << 7) + kk;
    g_Wth[dst] = hi;
    g_Wtl[dst] = __float2bfloat16(lo);
}

// ---------------- tensor-core node GEMM (bf16x2 3-pass, ~fp32 accurate) -----
// CTA 64 rows x 128 cols (X staged once). 8 warps, warp tile m32 x n32
// (rblk = wid>>2, cblk = wid&3): 512 ldmatrix/CTA vs 640 for m16n64.
// Same 3-pass math, same per-output k-order -> bit-identical results.
#define SGT_XH 0
#define SGT_XL 17408
#define SGT_WH 34816
#define SGT_WL 69632
#define SGT_BYTES 104448

__global__ void __launch_bounds__(256, 2) k_sgemm_tc(
    const float* __restrict__ Aext, int a_sel, int out_sel, int layer,
    const float* __restrict__ bias, int M) {
    extern __shared__ char smc[];
    const float* Ain = a_sel ? g_h : Aext;

    int tid = threadIdx.x;
    int lane = tid & 31, wid = tid >> 5;
    int rowBase = blockIdx.x * 64;

    // --- stage X split (64 x 128 fp32 -> hi/lo bf16, stride 136) ------------
    {
        const float4* A4 = (const float4*)Ain;
        uint32_t* Xh32 = (uint32_t*)(smc + SGT_XH);
        uint32_t* Xl32 = (uint32_t*)(smc + SGT_XL);
#pragma unroll
        for (int i = 0; i < 8; i++) {
            int idx = tid + i * 256;
            int rr = idx >> 5, c4 = idx & 31;
            float4 v = make_float4(0.f, 0.f, 0.f, 0.f);
            if (rowBase + rr < M) v = A4[(rowBase + rr) * 32 + c4];
            __nv_bfloat16 h0 = __float2bfloat16(v.x);
            __nv_bfloat16 h1 = __float2bfloat16(v.y);
            __nv_bfloat16 h2 = __float2bfloat16(v.z);
            __nv_bfloat16 h3 = __float2bfloat16(v.w);
            uint32_t hp0 = (uint32_t)__bfloat16_as_ushort(h0) |
                           ((uint32_t)__bfloat16_as_ushort(h1) << 16);
            uint32_t hp1 = (uint32_t)__bfloat16_as_ushort(h2) |
                           ((uint32_t)__bfloat16_as_ushort(h3) << 16);
            uint32_t lp0 = pack_bf16(v.x - __bfloat162float(h0), v.y - __bfloat162float(h1));
            uint32_t lp1 = pack_bf16(v.z - __bfloat162float(h2), v.w - __bfloat162float(h3));
            int o = rr * 68 + c4 * 2;
            *(uint2*)&Xh32[o] = make_uint2(hp0, hp1);
            *(uint2*)&Xl32[o] = make_uint2(lp0, lp1);
        }
    }
    // --- stage W hi/lo (pre-transposed [n][k], 128 n-rows) -------------------
    {
        const uint4* Wh4 = (const uint4*)(g_Wth + layer * 16384);
        const uint4* Wl4 = (const uint4*)(g_Wtl + layer * 16384);
#pragma unroll
        for (int i = 0; i < 8; i++) {
            int idx = tid + i * 256;
            int rr = idx >> 4, c8 = idx & 15;
            *(uint4*)(smc + SGT_WH + rr * 272 + c8 * 16) = Wh4[rr * 16 + c8];
            *(uint4*)(smc + SGT_WL + rr * 272 + c8 * 16) = Wl4[rr * 16 + c8];
        }
    }
    __syncthreads();

    int g = lane >> 2, tg = lane & 3;
    int rblk = wid >> 2, cblk = wid & 3;   // m: 2 x 32 rows, n: 4 x 32 cols

    float acc[2][4][4];
#pragma unroll
    for (int mt = 0; mt < 2; mt++)
#pragma unroll
        for (int n = 0; n < 4; n++)
#pragma unroll
            for (int j = 0; j < 4; j++) acc[mt][n][j] = 0.f;

    uint32_t xh_sb = (uint32_t)__cvta_generic_to_shared(smc + SGT_XH);
    uint32_t xl_sb = (uint32_t)__cvta_generic_to_shared(smc + SGT_XL);
    uint32_t wh_sb = (uint32_t)__cvta_generic_to_shared(smc + SGT_WH);
    uint32_t wl_sb = (uint32_t)__cvta_generic_to_shared(smc + SGT_WL);

    int a_r = rblk * 32 + (lane & 7) + (lane & 8);
    int a_kel = (lane & 16) ? 8 : 0;
    uint32_t a_hi_base = xh_sb + (uint32_t)(a_r * 272 + a_kel * 2);
    uint32_t a_lo_base = xl_sb + (uint32_t)(a_r * 272 + a_kel * 2);
    int b_nloc = (lane & 7) + ((lane & 16) >> 1);
    int b_kel = (lane & 8);
    uint32_t b_rowoff = (uint32_t)((cblk * 32 + b_nloc) * 272 + b_kel * 2);

#pragma unroll
    for (int k = 0; k < 8; k++) {
        uint32_t ah[2][4], al[2][4];
        ldmx4(ah[0], a_hi_base + k * 32);
        ldmx4(ah[1], a_hi_base + 16 * 272 + k * 32);
        ldmx4(al[0], a_lo_base + k * 32);
        ldmx4(al[1], a_lo_base + 16 * 272 + k * 32);
        uint32_t bh[2][4], bl[2][4];
#pragma unroll
        for (int nb2 = 0; nb2 < 2; nb2++) {
            uint32_t off = b_rowoff + (uint32_t)(nb2 * 16 * 272) + k * 32;
            ldmx4(bh[nb2], wh_sb + off);
            ldmx4(bl[nb2], wl_sb + off);
        }
#pragma unroll
        for (int mt = 0; mt < 2; mt++)
#pragma unroll
            for (int nb = 0; nb < 4; nb++) {
                uint32_t b0h = bh[nb >> 1][(nb & 1) * 2], b1h = bh[nb >> 1][(nb & 1) * 2 + 1];
                uint32_t b0l = bl[nb >> 1][(nb & 1) * 2], b1l = bl[nb >> 1][(nb & 1) * 2 + 1];
                mma_bf16(acc[mt][nb], ah[mt], b0h, b1h);
                mma_bf16(acc[mt][nb], al[mt], b0h, b1h);
                mma_bf16(acc[mt][nb], ah[mt], b0l, b1l);
            }
    }

    // --- epilogue -------------------------------------------------------------
#pragma unroll
    for (int mt = 0; mt < 2; mt++) {
        int r0 = rowBase + rblk * 32 + mt * 16 + g;
        if (out_sel == 0) {
            __half2* oh = (__half2*)g_hwh;
#pragma unroll
            for (int nb = 0; nb < 4; nb++) {
                int c = cblk * 32 + nb * 8 + 2 * tg;
                if (r0 < M)
                    oh[(r0 * 128 + c) >> 1] = __floats2half2_rn(acc[mt][nb][0], acc[mt][nb][1]);
                if (r0 + 8 < M)
                    oh[((r0 + 8) * 128 + c) >> 1] = __floats2half2_rn(acc[mt][nb][2], acc[mt][nb][3]);
            }
        } else {
            float* out = (out_sel == 1) ? g_A : g_B;
#pragma unroll
            for (int nb = 0; nb < 4; nb++) {
                int c = cblk * 32 + nb * 8 + 2 * tg;
                float bv0 = 0.f, bv1 = 0.f;
                if (bias) { bv0 = bias[c]; bv1 = bias[c + 1]; }
                if (r0 < M)
                    *(float2*)&out[r0 * 128 + c] = make_float2(acc[mt][nb][0] + bv0, acc[mt][nb][1] + bv1);
                if (r0 + 8 < M)
                    *(float2*)&out[(r0 + 8) * 128 + c] = make_float2(acc[mt][nb][2] + bv0, acc[mt][nb][3] + bv1);
            }
        }
    }
}

// ---------------- aggregation: h[n] = relu(self + sum + bias (+res)) --------
// 2 nodes per warp, 16 lanes per node, uint4 (8 fp16 ch) per lane.
__global__ void k_agg(const float* __restrict__ bias, int residual) {
    int gw = (blockIdx.x * blockDim.x + threadIdx.x) >> 5;
    int lane = threadIdx.x & 31;
    int half = lane >> 4, hl = lane & 15;
    int n = gw * 2 + half;
    if (n >= N_NODES) return;

    const uint4* hw4 = (const uint4*)g_hwh;
    float d = g_dis[n];
    float ds = d * d;
    float4 acc0 = make_float4(0.f, 0.f, 0.f, 0.f);
    float4 acc1 = make_float4(0.f, 0.f, 0.f, 0.f);
    acc_h8(acc0, acc1, hw4[n * 16 + hl], ds);

    int e = g_indptr[n];
    int end = g_indptr[n + 1];
    for (; e + 8 <= end; e += 8) {
        int s[8]; float nr[8]; uint4 v[8];
#pragma unroll
        for (int j = 0; j < 8; j++) { s[j] = g_csr_src[e + j]; nr[j] = g_csr_nrm[e + j]; }
#pragma unroll
        for (int j = 0; j < 8; j++) v[j] = hw4[s[j] * 16 + hl];
#pragma unroll
        for (int j = 0; j < 8; j++) acc_h8(acc0, acc1, v[j], nr[j]);
    }
    if (e + 4 <= end) {
        int s[4]; float nr[4]; uint4 v[4];
#pragma unroll
        for (int j = 0; j < 4; j++) { s[j] = g_csr_src[e + j]; nr[j] = g_csr_nrm[e + j]; }
#pragma unroll
        for (int j = 0; j < 4; j++) v[j] = hw4[s[j] * 16 + hl];
#pragma unroll
        for (int j = 0; j < 4; j++) acc_h8(acc0, acc1, v[j], nr[j]);
        e += 4;
    }
    for (; e < end; e++)
        acc_h8(acc0, acc1, hw4[g_csr_src[e] * 16 + hl], g_csr_nrm[e]);

    float4 b0 = ((const float4*)bias)[hl * 2];
    float4 b1 = ((const float4*)bias)[hl * 2 + 1];
    acc0 = f4add(acc0, b0);
    acc1 = f4add(acc1, b1);
    if (residual) {
        acc0 = f4add(acc0, ((const float4*)g_h)[n * 32 + hl * 2]);
        acc1 = f4add(acc1, ((const float4*)g_h)[n * 32 + hl * 2 + 1]);
    }
    ((float4*)g_h)[n * 32 + hl * 2] = f4relu(acc0);
    ((float4*)g_h)[n * 32 + hl * 2 + 1] = f4relu(acc1);
}

// ---------------- persistent fused edge MLP (mma.sync fp16, k16) ------------
// CTA = 4 independent 2-warp groups; each group processes 32-edge CSR tiles,
// synced by a named barrier (64 threads). Gather of one group overlaps MMA of
// others. Per-edge arithmetic identical to the 128-edge-tile version.
#define ESM_US 0
#define ESM_WS 34816
#define ESM_B1 69632
#define ESM_W2 70144
#define ESM_PB 70656        // 4 groups x 2 wings x 32 floats = 1024 B
#define ESM_BYTES 71680
#define N_TILES32 (N_EDGES / 32)
#define EDGE_GRID 296

__global__ void __launch_bounds__(256, 2) k_edge_mlp_fp16(
    const float* __restrict__ W1, const float* __restrict__ b1,
    const float* __restrict__ w2, const float* __restrict__ b2,
    float* __restrict__ out) {
    extern __shared__ char smc[];
    __half* Ws  = (__half*)(smc + ESM_WS);
    float* b1s  = (float*)(smc + ESM_B1);
    float* w2s  = (float*)(smc + ESM_W2);
    float* pbuf = (float*)(smc + ESM_PB);

    int tid = threadIdx.x;
    int lane = tid & 31, wid = tid >> 5;

    // --- stage W1^T (fp16), b1, w2 ONCE --------------------------------------
#pragma unroll 4
    for (int it = 0; it < 64; it++) {
        int i = it * 256 + tid;
        int kk = i >> 7, n = i & 127;
        Ws[n * 136 + kk] = __float2half_rn(W1[i]);
    }
    if (tid < 128) { b1s[tid] = b1[tid]; w2s[tid] = w2[tid]; }
    float b2v = b2[0];
    __syncthreads();

    int grp = wid >> 1;          // 0..3: independent 2-warp group
    int wing = wid & 1;          // n-half within group
    int gt = tid & 63;           // thread id within group
    int g = lane >> 2, tg = lane & 3;
    int barid = 1 + grp;

    uint32_t us_sb = (uint32_t)__cvta_generic_to_shared(smc + ESM_US);
    uint32_t ws_sb = (uint32_t)__cvta_generic_to_shared(smc + ESM_WS);
    uint32_t a_base = us_sb +
        (uint32_t)((grp * 32 + (lane & 7) + (lane & 8)) * 272 + ((lane & 16) ? 16 : 0));
    uint32_t b_base = ws_sb +
        (uint32_t)((wing * 64 + (lane & 7) + ((lane & 16) >> 1)) * 272 + (lane & 8) * 2);
    float* mypbuf = pbuf + grp * 64;

    const float4* A4 = (const float4*)g_A;
    const float4* B4 = (const float4*)g_B;

    for (int tile = blockIdx.x * 4 + grp; tile < N_TILES32; tile += EDGE_GRID * 4) {
        int p0 = tile * 32;

        // --- gather u = relu(A[src]+B[dst]) for 32 edges; 2 thr/edge --------
        {
            int i = gt >> 1, h = gt & 1;
            int p = p0 + i;
            int r = g_csr_src[p] * 32, c = g_csr_dst[p] * 32;
            __half2* dst = (__half2*)(smc + ESM_US + (grp * 32 + i) * 272 + h * 128);
#pragma unroll
            for (int q = 0; q < 16; q++) {
                float4 a = A4[r + h * 16 + q];
                float4 b = B4[c + h * 16 + q];
                dst[q * 2 + 0] = __floats2half2_rn(fmaxf(a.x + b.x, 0.f),
                                                   fmaxf(a.y + b.y, 0.f));
                dst[q * 2 + 1] = __floats2half2_rn(fmaxf(a.z + b.z, 0.f),
                                                   fmaxf(a.w + b.w, 0.f));
            }
        }
        asm volatile("bar.sync %0, 64;" :: "r"(barid) : "memory");

        // --- fp16 mma: warp covers m32 (its 32 edges) x n64 (its wing) -------
        float acc[2][8][4];
#pragma unroll
        for (int mt = 0; mt < 2; mt++)
#pragma unroll
            for (int n = 0; n < 8; n++)
#pragma unroll
                for (int j = 0; j < 4; j++) acc[mt][n][j] = 0.f;

#pragma unroll
        for (int k = 0; k < 8; k++) {
            uint32_t a0[4], a1[4];
            ldmx4(a0, a_base + k * 32);
            ldmx4(a1, a_base + 16 * 272 + k * 32);
            uint32_t bf[4][4];
#pragma unroll
            for (int nb2 = 0; nb2 < 4; nb2++)
                ldmx4(bf[nb2], b_base + (uint32_t)(nb2 * 16 * 272) + k * 32);
#pragma unroll
            for (int nb = 0; nb < 8; nb++) {
                uint32_t bb0 = bf[nb >> 1][(nb & 1) * 2];
                uint32_t bb1 = bf[nb >> 1][(nb & 1) * 2 + 1];
                mma_fp16(acc[0][nb], a0, bb0, bb1);
                mma_fp16(acc[1][nb], a1, bb0, bb1);
            }
        }

        // --- epilogue: relu(+b1).w2 dot, quad reduce, wing partials ----------
#pragma unroll
        for (int mt = 0; mt < 2; mt++) {
            float p0v = 0.f, p1v = 0.f;
#pragma unroll
            for (int nb = 0; nb < 8; nb++) {
                int c0 = wing * 64 + nb * 8 + 2 * tg;
                float wv0 = w2s[c0], wv1 = w2s[c0 + 1];
                float bb0 = b1s[c0], bb1 = b1s[c0 + 1];
                p0v += fmaxf(acc[mt][nb][0] + bb0, 0.f) * wv0 + fmaxf(acc[mt][nb][1] + bb1, 0.f) * wv1;
                p1v += fmaxf(acc[mt][nb][2] + bb0, 0.f) * wv0 + fmaxf(acc[mt][nb][3] + bb1, 0.f) * wv1;
            }
            p0v += __shfl_xor_sync(0xffffffffu, p0v, 1);
            p0v += __shfl_xor_sync(0xffffffffu, p0v, 2);
            p1v += __shfl_xor_sync(0xffffffffu, p1v, 1);
            p1v += __shfl_xor_sync(0xffffffffu, p1v, 2);
            if (tg == 0) {
                int rr = mt * 16 + g;
                mypbuf[wing * 32 + rr] = p0v;
                mypbuf[wing * 32 + rr + 8] = p1v;
            }
        }
        asm volatile("bar.sync %0, 64;" :: "r"(barid) : "memory");
        if (gt < 32)
            out[g_csr_eid[p0 + gt]] = mypbuf[gt] + mypbuf[32 + gt] + b2v;
    }
}

// ---------------- launch -----------------------------------------------------
extern "C" void kernel_launch(void* const* d_in, const int* in_sizes, int n_in,
                              void* d_out, int out_size) {
    const float* x       = (const float*)d_in[0];
    const int*   ei      = (const int*)d_in[1];
    const float* convs_W = (const float*)d_in[2];
    const float* convs_b = (const float*)d_in[3];
    const float* fc0_W   = (const float*)d_in[4];
    const float* fc0_b   = (const float*)d_in[5];
    const float* fc1_W   = (const float*)d_in[6];
    const float* fc1_b   = (const float*)d_in[7];
    const float* fc2_W   = (const float*)d_in[8];
    const float* fc2_b   = (const float*)d_in[9];
    float* out = (float*)d_out;

    const int* row = ei;
    const int* col = ei + N_EDGES;

    cudaFuncSetAttribute(k_sgemm_tc, cudaFuncAttributeMaxDynamicSharedMemorySize, SGT_BYTES);
    cudaFuncSetAttribute(k_edge_mlp_fp16, cudaFuncAttributeMaxDynamicSharedMemorySize, ESM_BYTES);

    const int GRID_GEMM = (N_NODES + 63) / 64;
    const int GRID_AGG = (N_NODES * 16 + 255) / 256;

    // 1. setup (sgemm L0 in the profiled 4th slot)
    k_split_w<<<(10 * 16384 + 255) / 256, 256>>>(convs_W, fc0_W);
    k_zero_deg<<<(N_NODES + 255) / 256, 256>>>();
    k_count_deg<<<(N_EDGES + 255) / 256, 256>>>(col);
    k_sgemm_tc<<<GRID_GEMM, 256, SGT_BYTES>>>(x, 0, 0, 0, nullptr, N_NODES);   // L0 GEMM
    k_scan_dis<<<1, 1024>>>();
    k_fill_csr<<<(N_EDGES + 255) / 256, 256>>>(row, col);
    k_agg<<<GRID_AGG, 256>>>(convs_b, 0);                                      // L0 agg

    // 2. GCN layers 1..7
    for (int l = 1; l < N_LAYERS; l++) {
        k_sgemm_tc<<<GRID_GEMM, 256, SGT_BYTES>>>(x, 1, 0, l, nullptr, N_NODES);
        k_agg<<<GRID_AGG, 256>>>(convs_b + l * CDIM, 1);
    }

    // 3. factorized fc0: A = h@W0a + b0, B = h@W0b
    k_sgemm_tc<<<GRID_GEMM, 256, SGT_BYTES>>>(nullptr, 1, 1, 8, fc0_b, N_NODES);
    k_sgemm_tc<<<GRID_GEMM, 256, SGT_BYTES>>>(nullptr, 1, 2, 9, nullptr, N_NODES);

    // 4. persistent fused edge MLP, CSR order, 4 independent groups/CTA
    k_edge_mlp_fp16<<<EDGE_GRID, 256, ESM_BYTES>>>(fc1_W, fc1_b, fc2_W, fc2_b, out);
}

// round 16
// speedup vs baseline: 1.5402x; 1.0169x over previous
#include <cuda_runtime.h>
#include <cuda_bf16.h>
#include <cuda_fp16.h>
#include <cstdint>

#define N_NODES 50000
#define N_EDGES 1600000
#define CDIM 128
#define N_LAYERS 8

// ---------------- scratch (device globals; no allocation allowed) ----------
__device__ float  g_h [N_NODES * CDIM];    // fp32 node features (residual / fc0 input)
__device__ __half g_hwh[N_NODES * CDIM];   // fp16 transformed features (gather table)
__device__ float  g_A [N_NODES * CDIM];
__device__ float  g_B [N_NODES * CDIM];
__device__ float  g_dis[N_NODES];
__device__ int    g_deg[N_NODES];
__device__ int    g_indptr[N_NODES + 1];
__device__ int    g_cursor[N_NODES];
__device__ int    g_csr_src[N_EDGES];
__device__ int    g_csr_dst[N_EDGES];
__device__ int    g_csr_eid[N_EDGES];
__device__ float  g_csr_nrm[N_EDGES];
// transposed + bf16 hi/lo-split weights for node GEMMs: [10][n=128][k=128]
__device__ __nv_bfloat16 g_Wth[10 * 128 * 128];
__device__ __nv_bfloat16 g_Wtl[10 * 128 * 128];

// ---------------- helpers ----------------------------------------------------
__device__ __forceinline__ void mma_bf16(float d[4], const uint32_t a[4],
                                         uint32_t b0, uint32_t b1) {
    asm volatile(
        "mma.sync.aligned.m16n8k16.row.col.f32.bf16.bf16.f32 "
        "{%0,%1,%2,%3}, {%4,%5,%6,%7}, {%8,%9}, {%0,%1,%2,%3};"
        : "+f"(d[0]), "+f"(d[1]), "+f"(d[2]), "+f"(d[3])
        : "r"(a[0]), "r"(a[1]), "r"(a[2]), "r"(a[3]), "r"(b0), "r"(b1));
}
__device__ __forceinline__ void mma_fp16(float d[4], const uint32_t a[4],
                                         uint32_t b0, uint32_t b1) {
    asm volatile(
        "mma.sync.aligned.m16n8k16.row.col.f32.f16.f16.f32 "
        "{%0,%1,%2,%3}, {%4,%5,%6,%7}, {%8,%9}, {%0,%1,%2,%3};"
        : "+f"(d[0]), "+f"(d[1]), "+f"(d[2]), "+f"(d[3])
        : "r"(a[0]), "r"(a[1]), "r"(a[2]), "r"(a[3]), "r"(b0), "r"(b1));
}
__device__ __forceinline__ void ldmx4(uint32_t r[4], uint32_t addr) {
    asm volatile("ldmatrix.sync.aligned.m8n8.x4.shared.b16 {%0,%1,%2,%3}, [%4];"
                 : "=r"(r[0]), "=r"(r[1]), "=r"(r[2]), "=r"(r[3]) : "r"(addr));
}
__device__ __forceinline__ float4 f4add(float4 a, float4 b) {
    return make_float4(a.x + b.x, a.y + b.y, a.z + b.z, a.w + b.w);
}
__device__ __forceinline__ float4 f4relu(float4 a) {
    return make_float4(fmaxf(a.x, 0.f), fmaxf(a.y, 0.f), fmaxf(a.z, 0.f), fmaxf(a.w, 0.f));
}
__device__ __forceinline__ uint32_t pack_bf16(float a, float b) {
    uint32_t lo = (uint32_t)__bfloat16_as_ushort(__float2bfloat16(a));
    uint32_t hi = (uint32_t)__bfloat16_as_ushort(__float2bfloat16(b));
    return lo | (hi << 16);
}
// accumulate 8 fp16 channels (uint4) scaled by nr into two float4s
__device__ __forceinline__ void acc_h8(float4& a0, float4& a1, uint4 raw, float nr) {
    __half2 h0 = *(__half2*)&raw.x;
    __half2 h1 = *(__half2*)&raw.y;
    __half2 h2 = *(__half2*)&raw.z;
    __half2 h3 = *(__half2*)&raw.w;
    float2 f0 = __half22float2(h0);
    float2 f1 = __half22float2(h1);
    float2 f2 = __half22float2(h2);
    float2 f3 = __half22float2(h3);
    a0.x += nr * f0.x; a0.y += nr * f0.y;
    a0.z += nr * f1.x; a0.w += nr * f1.y;
    a1.x += nr * f2.x; a1.y += nr * f2.y;
    a1.z += nr * f3.x; a1.w += nr * f3.y;
}

// ---------------- setup kernels ---------------------------------------------
__global__ void k_zero_deg() {
    int i = blockIdx.x * blockDim.x + threadIdx.x;
    if (i < N_NODES) g_deg[i] = 0;
}

__global__ void k_count_deg(const int* __restrict__ col) {
    int e = blockIdx.x * blockDim.x + threadIdx.x;
    if (e < N_EDGES) atomicAdd(&g_deg[col[e]], 1);
}

// warp-shuffle based scan: 3 syncs per 1024-chunk
__global__ void k_scan_dis() {
    __shared__ int wsum[32];
    __shared__ int s_carry;
    int t = threadIdx.x, lane = t & 31, wd = t >> 5;
    if (t == 0) s_carry = 0;
    __syncthreads();
    for (int base = 0; base < N_NODES; base += 1024) {
        int idx = base + t;
        int v = (idx < N_NODES) ? g_deg[idx] : 0;
        int x = v;
#pragma unroll
        for (int off = 1; off < 32; off <<= 1) {
            int y = __shfl_up_sync(0xffffffffu, x, off);
            if (lane >= off) x += y;
        }
        if (lane == 31) wsum[wd] = x;
        __syncthreads();
        if (wd == 0) {
            int w = wsum[lane];
#pragma unroll
            for (int off = 1; off < 32; off <<= 1) {
                int y = __shfl_up_sync(0xffffffffu, w, off);
                if (lane >= off) w += y;
            }
            wsum[lane] = w;
        }
        __syncthreads();
        int warp_prefix = (wd == 0) ? 0 : wsum[wd - 1];
        int incl = warp_prefix + x;
        int carry = s_carry;
        if (idx < N_NODES) {
            int excl = carry + incl - v;
            g_indptr[idx] = excl;
            g_cursor[idx] = excl;
            g_dis[idx] = rsqrtf((float)(v + 1));
        }
        __syncthreads();
        if (t == 1023) s_carry = carry + incl;
        __syncthreads();
    }
    if (t == 0) g_indptr[N_NODES] = s_carry;
}

__global__ void k_fill_csr(const int* __restrict__ row, const int* __restrict__ col) {
    int e = blockIdx.x * blockDim.x + threadIdx.x;
    if (e < N_EDGES) {
        int r = row[e], c = col[e];
        float nrm = g_dis[r] * g_dis[c];
        int pos = atomicAdd(&g_cursor[c], 1);
        g_csr_src[pos] = r;
        g_csr_dst[pos] = c;
        g_csr_eid[pos] = e;
        g_csr_nrm[pos] = nrm;
    }
}

// ---------------- W transpose + bf16 hi/lo split (once) ---------------------
__global__ void k_split_w(const float* __restrict__ convs_W,
                          const float* __restrict__ fc0_W) {
    int idx = blockIdx.x * 256 + threadIdx.x;
    if (idx >= 10 * 16384) return;
    int l = idx >> 14;
    int kk = (idx >> 7) & 127;
    int n = idx & 127;
    float v = (l < 8) ? convs_W[idx] : fc0_W[idx - 8 * 16384];
    __nv_bfloat16 hi = __float2bfloat16(v);
    float lo = v - __bfloat162float(hi);
    int dst = (l << 14) + (n << 7) + kk;
    g_Wth[dst] = hi;
    g_Wtl[dst] = __float2bfloat16(lo);
}

// ---------------- persistent tensor-core node GEMM (bf16x2 3-pass) ----------
// 296 CTAs loop over 64-row tiles. W hi/lo staged once per CTA (conv/fc0
// single), or per-pass for fc0 dual mode. Warp tile m32 x n32. Bit-identical
// 3-pass math to previous rounds.
#define SGT_XH 0
#define SGT_XL 17408
#define SGT_WH 34816
#define SGT_WL 69632
#define SGT_BYTES 104448
#define GEMM_GRID 296
#define N_ROWTILES ((N_NODES + 63) / 64)

__device__ __forceinline__ void gemm_stage_X(char* smc, const float* __restrict__ Ain,
                                             int rowBase, int tid, int M) {
    const float4* A4 = (const float4*)Ain;
    uint32_t* Xh32 = (uint32_t*)(smc + SGT_XH);
    uint32_t* Xl32 = (uint32_t*)(smc + SGT_XL);
#pragma unroll
    for (int i = 0; i < 8; i++) {
        int idx = tid + i * 256;
        int rr = idx >> 5, c4 = idx & 31;
        float4 v = make_float4(0.f, 0.f, 0.f, 0.f);
        if (rowBase + rr < M) v = A4[(rowBase + rr) * 32 + c4];
        __nv_bfloat16 h0 = __float2bfloat16(v.x);
        __nv_bfloat16 h1 = __float2bfloat16(v.y);
        __nv_bfloat16 h2 = __float2bfloat16(v.z);
        __nv_bfloat16 h3 = __float2bfloat16(v.w);
        uint32_t hp0 = (uint32_t)__bfloat16_as_ushort(h0) |
                       ((uint32_t)__bfloat16_as_ushort(h1) << 16);
        uint32_t hp1 = (uint32_t)__bfloat16_as_ushort(h2) |
                       ((uint32_t)__bfloat16_as_ushort(h3) << 16);
        uint32_t lp0 = pack_bf16(v.x - __bfloat162float(h0), v.y - __bfloat162float(h1));
        uint32_t lp1 = pack_bf16(v.z - __bfloat162float(h2), v.w - __bfloat162float(h3));
        int o = rr * 68 + c4 * 2;
        *(uint2*)&Xh32[o] = make_uint2(hp0, hp1);
        *(uint2*)&Xl32[o] = make_uint2(lp0, lp1);
    }
}

__device__ __forceinline__ void gemm_stage_W(char* smc, int layer, int tid) {
    const uint4* Wh4 = (const uint4*)(g_Wth + layer * 16384);
    const uint4* Wl4 = (const uint4*)(g_Wtl + layer * 16384);
#pragma unroll
    for (int i = 0; i < 8; i++) {
        int idx = tid + i * 256;
        int rr = idx >> 4, c8 = idx & 15;
        *(uint4*)(smc + SGT_WH + rr * 272 + c8 * 16) = Wh4[rr * 16 + c8];
        *(uint4*)(smc + SGT_WL + rr * 272 + c8 * 16) = Wl4[rr * 16 + c8];
    }
}

__device__ __forceinline__ void gemm_tile_mma(char* smc, int lane, int wid,
                                              float acc[2][4][4]) {
#pragma unroll
    for (int mt = 0; mt < 2; mt++)
#pragma unroll
        for (int n = 0; n < 4; n++)
#pragma unroll
            for (int j = 0; j < 4; j++) acc[mt][n][j] = 0.f;

    int rblk = wid >> 2, cblk = wid & 3;
    uint32_t xh_sb = (uint32_t)__cvta_generic_to_shared(smc + SGT_XH);
    uint32_t xl_sb = (uint32_t)__cvta_generic_to_shared(smc + SGT_XL);
    uint32_t wh_sb = (uint32_t)__cvta_generic_to_shared(smc + SGT_WH);
    uint32_t wl_sb = (uint32_t)__cvta_generic_to_shared(smc + SGT_WL);

    int a_r = rblk * 32 + (lane & 7) + (lane & 8);
    int a_kel = (lane & 16) ? 8 : 0;
    uint32_t a_hi_base = xh_sb + (uint32_t)(a_r * 272 + a_kel * 2);
    uint32_t a_lo_base = xl_sb + (uint32_t)(a_r * 272 + a_kel * 2);
    int b_nloc = (lane & 7) + ((lane & 16) >> 1);
    int b_kel = (lane & 8);
    uint32_t b_rowoff = (uint32_t)((cblk * 32 + b_nloc) * 272 + b_kel * 2);

#pragma unroll
    for (int k = 0; k < 8; k++) {
        uint32_t ah[2][4], al[2][4];
        ldmx4(ah[0], a_hi_base + k * 32);
        ldmx4(ah[1], a_hi_base + 16 * 272 + k * 32);
        ldmx4(al[0], a_lo_base + k * 32);
        ldmx4(al[1], a_lo_base + 16 * 272 + k * 32);
        uint32_t bh[2][4], bl[2][4];
#pragma unroll
        for (int nb2 = 0; nb2 < 2; nb2++) {
            uint32_t off = b_rowoff + (uint32_t)(nb2 * 16 * 272) + k * 32;
            ldmx4(bh[nb2], wh_sb + off);
            ldmx4(bl[nb2], wl_sb + off);
        }
#pragma unroll
        for (int mt = 0; mt < 2; mt++)
#pragma unroll
            for (int nb = 0; nb < 4; nb++) {
                uint32_t b0h = bh[nb >> 1][(nb & 1) * 2], b1h = bh[nb >> 1][(nb & 1) * 2 + 1];
                uint32_t b0l = bl[nb >> 1][(nb & 1) * 2], b1l = bl[nb >> 1][(nb & 1) * 2 + 1];
                mma_bf16(acc[mt][nb], ah[mt], b0h, b1h);
                mma_bf16(acc[mt][nb], al[mt], b0h, b1h);
                mma_bf16(acc[mt][nb], ah[mt], b0l, b1l);
            }
    }
}

__device__ __forceinline__ void gemm_epi_fp32(float* __restrict__ out,
                                              const float* __restrict__ bias,
                                              int rowBase, int lane, int wid, int M,
                                              float acc[2][4][4]) {
    int g = lane >> 2, tg = lane & 3;
    int rblk = wid >> 2, cblk = wid & 3;
#pragma unroll
    for (int mt = 0; mt < 2; mt++) {
        int r0 = rowBase + rblk * 32 + mt * 16 + g;
#pragma unroll
        for (int nb = 0; nb < 4; nb++) {
            int c = cblk * 32 + nb * 8 + 2 * tg;
            float bv0 = 0.f, bv1 = 0.f;
            if (bias) { bv0 = bias[c]; bv1 = bias[c + 1]; }
            if (r0 < M)
                *(float2*)&out[r0 * 128 + c] = make_float2(acc[mt][nb][0] + bv0, acc[mt][nb][1] + bv1);
            if (r0 + 8 < M)
                *(float2*)&out[(r0 + 8) * 128 + c] = make_float2(acc[mt][nb][2] + bv0, acc[mt][nb][3] + bv1);
        }
    }
}

__device__ __forceinline__ void gemm_epi_fp16(int rowBase, int lane, int wid, int M,
                                              float acc[2][4][4]) {
    int g = lane >> 2, tg = lane & 3;
    int rblk = wid >> 2, cblk = wid & 3;
    __half2* oh = (__half2*)g_hwh;
#pragma unroll
    for (int mt = 0; mt < 2; mt++) {
        int r0 = rowBase + rblk * 32 + mt * 16 + g;
#pragma unroll
        for (int nb = 0; nb < 4; nb++) {
            int c = cblk * 32 + nb * 8 + 2 * tg;
            if (r0 < M)
                oh[(r0 * 128 + c) >> 1] = __floats2half2_rn(acc[mt][nb][0], acc[mt][nb][1]);
            if (r0 + 8 < M)
                oh[((r0 + 8) * 128 + c) >> 1] = __floats2half2_rn(acc[mt][nb][2], acc[mt][nb][3]);
        }
    }
}

// mode: 0 = conv layer (out g_hwh fp16), 3 = fc0 dual (g_A=bias pass W8, g_B pass W9)
__global__ void __launch_bounds__(256, 2) k_sgemm_tc(
    const float* __restrict__ Aext, int a_sel, int mode, int layer,
    const float* __restrict__ bias, int M) {
    extern __shared__ char smc[];
    const float* Ain = a_sel ? g_h : Aext;
    int tid = threadIdx.x;
    int lane = tid & 31, wid = tid >> 5;

    if (mode != 3) gemm_stage_W(smc, layer, tid);   // staged once per CTA

    float acc[2][4][4];
    for (int tile = blockIdx.x; tile < N_ROWTILES; tile += GEMM_GRID) {
        int rowBase = tile * 64;
        gemm_stage_X(smc, Ain, rowBase, tid, M);
        if (mode == 3) gemm_stage_W(smc, 8, tid);
        __syncthreads();

        gemm_tile_mma(smc, lane, wid, acc);
        if (mode == 3) {
            gemm_epi_fp32(g_A, bias, rowBase, lane, wid, M, acc);
            __syncthreads();                 // all mma reads of W8 done
            gemm_stage_W(smc, 9, tid);
            __syncthreads();
            gemm_tile_mma(smc, lane, wid, acc);
            gemm_epi_fp32(g_B, nullptr, rowBase, lane, wid, M, acc);
        } else {
            gemm_epi_fp16(rowBase, lane, wid, M, acc);
        }
        __syncthreads();                     // protect smem before next tile
    }
}

// ---------------- aggregation: h[n] = relu(self + sum + bias (+res)) --------
// 2 nodes per warp, 16 lanes per node, uint4 (8 fp16 ch) per lane.
__global__ void k_agg(const float* __restrict__ bias, int residual) {
    int gw = (blockIdx.x * blockDim.x + threadIdx.x) >> 5;
    int lane = threadIdx.x & 31;
    int half = lane >> 4, hl = lane & 15;
    int n = gw * 2 + half;
    if (n >= N_NODES) return;

    const uint4* hw4 = (const uint4*)g_hwh;
    float d = g_dis[n];
    float ds = d * d;
    float4 acc0 = make_float4(0.f, 0.f, 0.f, 0.f);
    float4 acc1 = make_float4(0.f, 0.f, 0.f, 0.f);
    acc_h8(acc0, acc1, hw4[n * 16 + hl], ds);

    int e = g_indptr[n];
    int end = g_indptr[n + 1];
    for (; e + 8 <= end; e += 8) {
        int s[8]; float nr[8]; uint4 v[8];
#pragma unroll
        for (int j = 0; j < 8; j++) { s[j] = g_csr_src[e + j]; nr[j] = g_csr_nrm[e + j]; }
#pragma unroll
        for (int j = 0; j < 8; j++) v[j] = hw4[s[j] * 16 + hl];
#pragma unroll
        for (int j = 0; j < 8; j++) acc_h8(acc0, acc1, v[j], nr[j]);
    }
    if (e + 4 <= end) {
        int s[4]; float nr[4]; uint4 v[4];
#pragma unroll
        for (int j = 0; j < 4; j++) { s[j] = g_csr_src[e + j]; nr[j] = g_csr_nrm[e + j]; }
#pragma unroll
        for (int j = 0; j < 4; j++) v[j] = hw4[s[j] * 16 + hl];
#pragma unroll
        for (int j = 0; j < 4; j++) acc_h8(acc0, acc1, v[j], nr[j]);
        e += 4;
    }
    for (; e < end; e++)
        acc_h8(acc0, acc1, hw4[g_csr_src[e] * 16 + hl], g_csr_nrm[e]);

    float4 b0 = ((const float4*)bias)[hl * 2];
    float4 b1 = ((const float4*)bias)[hl * 2 + 1];
    acc0 = f4add(acc0, b0);
    acc1 = f4add(acc1, b1);
    if (residual) {
        acc0 = f4add(acc0, ((const float4*)g_h)[n * 32 + hl * 2]);
        acc1 = f4add(acc1, ((const float4*)g_h)[n * 32 + hl * 2 + 1]);
    }
    ((float4*)g_h)[n * 32 + hl * 2] = f4relu(acc0);
    ((float4*)g_h)[n * 32 + hl * 2 + 1] = f4relu(acc1);
}

// ---------------- persistent fused edge MLP (mma.sync fp16, k16) ------------
// CTA = 4 independent 2-warp groups; 32-edge CSR tiles, named barriers.
#define ESM_US 0
#define ESM_WS 34816
#define ESM_B1 69632
#define ESM_W2 70144
#define ESM_PB 70656
#define ESM_BYTES 71680
#define N_TILES32 (N_EDGES / 32)
#define EDGE_GRID 296

__global__ void __launch_bounds__(256, 2) k_edge_mlp_fp16(
    const float* __restrict__ W1, const float* __restrict__ b1,
    const float* __restrict__ w2, const float* __restrict__ b2,
    float* __restrict__ out) {
    extern __shared__ char smc[];
    __half* Ws  = (__half*)(smc + ESM_WS);
    float* b1s  = (float*)(smc + ESM_B1);
    float* w2s  = (float*)(smc + ESM_W2);
    float* pbuf = (float*)(smc + ESM_PB);

    int tid = threadIdx.x;
    int lane = tid & 31, wid = tid >> 5;

#pragma unroll 4
    for (int it = 0; it < 64; it++) {
        int i = it * 256 + tid;
        int kk = i >> 7, n = i & 127;
        Ws[n * 136 + kk] = __float2half_rn(W1[i]);
    }
    if (tid < 128) { b1s[tid] = b1[tid]; w2s[tid] = w2[tid]; }
    float b2v = b2[0];
    __syncthreads();

    int grp = wid >> 1;
    int wing = wid & 1;
    int gt = tid & 63;
    int g = lane >> 2, tg = lane & 3;
    int barid = 1 + grp;

    uint32_t us_sb = (uint32_t)__cvta_generic_to_shared(smc + ESM_US);
    uint32_t ws_sb = (uint32_t)__cvta_generic_to_shared(smc + ESM_WS);
    uint32_t a_base = us_sb +
        (uint32_t)((grp * 32 + (lane & 7) + (lane & 8)) * 272 + ((lane & 16) ? 16 : 0));
    uint32_t b_base = ws_sb +
        (uint32_t)((wing * 64 + (lane & 7) + ((lane & 16) >> 1)) * 272 + (lane & 8) * 2);
    float* mypbuf = pbuf + grp * 64;

    const float4* A4 = (const float4*)g_A;
    const float4* B4 = (const float4*)g_B;

    for (int tile = blockIdx.x * 4 + grp; tile < N_TILES32; tile += EDGE_GRID * 4) {
        int p0 = tile * 32;

        {
            int i = gt >> 1, h = gt & 1;
            int p = p0 + i;
            int r = g_csr_src[p] * 32, c = g_csr_dst[p] * 32;
            __half2* dst = (__half2*)(smc + ESM_US + (grp * 32 + i) * 272 + h * 128);
#pragma unroll
            for (int q = 0; q < 16; q++) {
                float4 a = A4[r + h * 16 + q];
                float4 b = B4[c + h * 16 + q];
                dst[q * 2 + 0] = __floats2half2_rn(fmaxf(a.x + b.x, 0.f),
                                                   fmaxf(a.y + b.y, 0.f));
                dst[q * 2 + 1] = __floats2half2_rn(fmaxf(a.z + b.z, 0.f),
                                                   fmaxf(a.w + b.w, 0.f));
            }
        }
        asm volatile("bar.sync %0, 64;" :: "r"(barid) : "memory");

        float acc[2][8][4];
#pragma unroll
        for (int mt = 0; mt < 2; mt++)
#pragma unroll
            for (int n = 0; n < 8; n++)
#pragma unroll
                for (int j = 0; j < 4; j++) acc[mt][n][j] = 0.f;

#pragma unroll
        for (int k = 0; k < 8; k++) {
            uint32_t a0[4], a1[4];
            ldmx4(a0, a_base + k * 32);
            ldmx4(a1, a_base + 16 * 272 + k * 32);
            uint32_t bf[4][4];
#pragma unroll
            for (int nb2 = 0; nb2 < 4; nb2++)
                ldmx4(bf[nb2], b_base + (uint32_t)(nb2 * 16 * 272) + k * 32);
#pragma unroll
            for (int nb = 0; nb < 8; nb++) {
                uint32_t bb0 = bf[nb >> 1][(nb & 1) * 2];
                uint32_t bb1 = bf[nb >> 1][(nb & 1) * 2 + 1];
                mma_fp16(acc[0][nb], a0, bb0, bb1);
                mma_fp16(acc[1][nb], a1, bb0, bb1);
            }
        }

#pragma unroll
        for (int mt = 0; mt < 2; mt++) {
            float p0v = 0.f, p1v = 0.f;
#pragma unroll
            for (int nb = 0; nb < 8; nb++) {
                int c0 = wing * 64 + nb * 8 + 2 * tg;
                float wv0 = w2s[c0], wv1 = w2s[c0 + 1];
                float bb0 = b1s[c0], bb1 = b1s[c0 + 1];
                p0v += fmaxf(acc[mt][nb][0] + bb0, 0.f) * wv0 + fmaxf(acc[mt][nb][1] + bb1, 0.f) * wv1;
                p1v += fmaxf(acc[mt][nb][2] + bb0, 0.f) * wv0 + fmaxf(acc[mt][nb][3] + bb1, 0.f) * wv1;
            }
            p0v += __shfl_xor_sync(0xffffffffu, p0v, 1);
            p0v += __shfl_xor_sync(0xffffffffu, p0v, 2);
            p1v += __shfl_xor_sync(0xffffffffu, p1v, 1);
            p1v += __shfl_xor_sync(0xffffffffu, p1v, 2);
            if (tg == 0) {
                int rr = mt * 16 + g;
                mypbuf[wing * 32 + rr] = p0v;
                mypbuf[wing * 32 + rr + 8] = p1v;
            }
        }
        asm volatile("bar.sync %0, 64;" :: "r"(barid) : "memory");
        if (gt < 32)
            out[g_csr_eid[p0 + gt]] = mypbuf[gt] + mypbuf[32 + gt] + b2v;
    }
}

// ---------------- launch -----------------------------------------------------
extern "C" void kernel_launch(void* const* d_in, const int* in_sizes, int n_in,
                              void* d_out, int out_size) {
    const float* x       = (const float*)d_in[0];
    const int*   ei      = (const int*)d_in[1];
    const float* convs_W = (const float*)d_in[2];
    const float* convs_b = (const float*)d_in[3];
    const float* fc0_W   = (const float*)d_in[4];
    const float* fc0_b   = (const float*)d_in[5];
    const float* fc1_W   = (const float*)d_in[6];
    const float* fc1_b   = (const float*)d_in[7];
    const float* fc2_W   = (const float*)d_in[8];
    const float* fc2_b   = (const float*)d_in[9];
    float* out = (float*)d_out;

    const int* row = ei;
    const int* col = ei + N_EDGES;

    cudaFuncSetAttribute(k_sgemm_tc, cudaFuncAttributeMaxDynamicSharedMemorySize, SGT_BYTES);
    cudaFuncSetAttribute(k_edge_mlp_fp16, cudaFuncAttributeMaxDynamicSharedMemorySize, ESM_BYTES);

    const int GRID_AGG = (N_NODES * 16 + 255) / 256;

    // 1. setup (persistent sgemm L0 in the profiled 4th slot)
    k_split_w<<<(10 * 16384 + 255) / 256, 256>>>(convs_W, fc0_W);
    k_zero_deg<<<(N_NODES + 255) / 256, 256>>>();
    k_count_deg<<<(N_EDGES + 255) / 256, 256>>>(col);
    k_sgemm_tc<<<GEMM_GRID, 256, SGT_BYTES>>>(x, 0, 0, 0, nullptr, N_NODES);   // L0 GEMM
    k_scan_dis<<<1, 1024>>>();
    k_fill_csr<<<(N_EDGES + 255) / 256, 256>>>(row, col);
    k_agg<<<GRID_AGG, 256>>>(convs_b, 0);                                      // L0 agg

    // 2. GCN layers 1..7
    for (int l = 1; l < N_LAYERS; l++) {
        k_sgemm_tc<<<GEMM_GRID, 256, SGT_BYTES>>>(x, 1, 0, l, nullptr, N_NODES);
        k_agg<<<GRID_AGG, 256>>>(convs_b + l * CDIM, 1);
    }

    // 3. fused fc0 dual GEMM: g_A = h@W8 + b0, g_B = h@W9 (X staged once)
    k_sgemm_tc<<<GEMM_GRID, 256, SGT_BYTES>>>(nullptr, 1, 3, 8, fc0_b, N_NODES);

    // 4. persistent fused edge MLP, CSR order, 4 independent groups/CTA
    k_edge_mlp_fp16<<<EDGE_GRID, 256, ESM_BYTES>>>(fc1_W, fc1_b, fc2_W, fc2_b, out);
}